// round 9
// baseline (speedup 1.0000x reference)
#include <cuda_runtime.h>
#include <cuda_bf16.h>
#include <cuda_fp16.h>
#include <math.h>

typedef unsigned int u32;
typedef unsigned long long u64;

#define BATCH 2
#define SEQ   2048
#define DIM   512
#define NHEAD 8
#define DK    64
#define MT    (BATCH*SEQ)
#define LOG2E 1.4426950408889634f
#define ONESF16 0x3C003C00u

// ---------------- global scratch (alloc-free) ------------------------------
__device__ __nv_bfloat16 gXh[MT*DIM], gXl[MT*DIM];
__device__ __nv_bfloat16 gWh[4][DIM*DIM], gWl[4][DIM*DIM];  // 0..2 = QKV (contig), 3 = O
__device__ __half gQ[MT*DIM];                // pre-scaled 0.125*log2e
__device__ __half gK[MT*DIM];
__device__ __half gV[MT*DIM];
__device__ __nv_bfloat16 gOh[MT*DIM], gOl[MT*DIM];
// expanded fp16-pair AND masks: [combo][row][tile(32)][t4(4)][f(8)] u32
__device__ u32 g_maskex[4u*SEQ*(SEQ/2)];

// ---------------- helpers ---------------------------------------------------
static __device__ __forceinline__ u32 smem_u32(const void* p) {
    u32 a; asm("{ .reg .u64 t; cvta.to.shared.u64 t, %1; cvt.u32.u64 %0, t; }" : "=r"(a) : "l"(p));
    return a;
}
static __device__ __forceinline__ float ex2f(float x) {
    float y; asm("ex2.approx.f32 %0, %1;" : "=f"(y) : "f"(x)); return y;
}
static __device__ __forceinline__ void split2(float v, __nv_bfloat16& hi, __nv_bfloat16& lo) {
    hi = __float2bfloat16(v);
    lo = __float2bfloat16(v - __bfloat162float(hi));
}
static __device__ __forceinline__ u32 packbf(__nv_bfloat16 a, __nv_bfloat16 b) {
    return (u32)__bfloat16_as_ushort(a) | ((u32)__bfloat16_as_ushort(b) << 16);
}
// packs {lo, hi} halves
static __device__ __forceinline__ u32 cvtf16x2(float lo, float hi) {
    u32 d; asm("cvt.rn.f16x2.f32 %0, %1, %2;" : "=r"(d) : "f"(hi), "f"(lo)); return d;
}

#define LDM4(r0,r1,r2,r3,a) \
    asm volatile("ldmatrix.sync.aligned.m8n8.x4.shared.b16 {%0,%1,%2,%3}, [%4];" \
        : "=r"(r0),"=r"(r1),"=r"(r2),"=r"(r3) : "r"(a))
#define LDM4T(r0,r1,r2,r3,a) \
    asm volatile("ldmatrix.sync.aligned.m8n8.x4.trans.shared.b16 {%0,%1,%2,%3}, [%4];" \
        : "=r"(r0),"=r"(r1),"=r"(r2),"=r"(r3) : "r"(a))
#define MMAB(d,a,b) \
    asm volatile("mma.sync.aligned.m16n8k16.row.col.f32.bf16.bf16.f32 " \
        "{%0,%1,%2,%3}, {%4,%5,%6,%7}, {%8,%9}, {%0,%1,%2,%3};" \
        : "+f"((d)[0]),"+f"((d)[1]),"+f"((d)[2]),"+f"((d)[3]) \
        : "r"((a)[0]),"r"((a)[1]),"r"((a)[2]),"r"((a)[3]),"r"((b)[0]),"r"((b)[1]))
#define MMAH(d,a,b) \
    asm volatile("mma.sync.aligned.m16n8k16.row.col.f32.f16.f16.f32 " \
        "{%0,%1,%2,%3}, {%4,%5,%6,%7}, {%8,%9}, {%0,%1,%2,%3};" \
        : "+f"((d)[0]),"+f"((d)[1]),"+f"((d)[2]),"+f"((d)[3]) \
        : "r"((a)[0]),"r"((a)[1]),"r"((a)[2]),"r"((a)[3]),"r"((b)[0]),"r"((b)[1]))
#define MMAH2(d,a,b0,b1) \
    asm volatile("mma.sync.aligned.m16n8k16.row.col.f32.f16.f16.f32 " \
        "{%0,%1,%2,%3}, {%4,%5,%6,%7}, {%8,%9}, {%0,%1,%2,%3};" \
        : "+f"((d)[0]),"+f"((d)[1]),"+f"((d)[2]),"+f"((d)[3]) \
        : "r"((a)[0]),"r"((a)[1]),"r"((a)[2]),"r"((a)[3]),"r"(b0),"r"(b1))

#define CPA16(d, s) asm volatile("cp.async.cg.shared.global [%0], [%1], 16;" :: "r"(d), "l"(s) : "memory")
#define CPCOMMIT()  asm volatile("cp.async.commit_group;" ::: "memory")
#define CPWAIT(n)   asm volatile("cp.async.wait_group %0;" :: "n"(n) : "memory")

// ---------------- fp32 -> (hi, lo) bf16 split: x + all weights, one launch --
__global__ void conv_all(const float* __restrict__ x,
                         const float* __restrict__ Wq, const float* __restrict__ Wk,
                         const float* __restrict__ Wv, const float* __restrict__ Wo) {
    int blk = blockIdx.x;
    const float* src;
    __nv_bfloat16 *dh, *dl;
    int i;
    if (blk < 2048) {                      // x: 2M elements
        src = x; dh = gXh; dl = gXl;
        i = (blk * 256 + threadIdx.x) * 4;
    } else {                               // weights: 256 blocks each
        int sel = (blk - 2048) >> 8, b2 = (blk - 2048) & 255;
        src = sel == 0 ? Wq : sel == 1 ? Wk : sel == 2 ? Wv : Wo;
        dh = gWh[sel]; dl = gWl[sel];
        i = (b2 * 256 + threadIdx.x) * 4;
    }
    float4 v = *(const float4*)(src + i);
    __nv_bfloat16 h0,l0,h1,l1,h2,l2,h3,l3;
    split2(v.x,h0,l0); split2(v.y,h1,l1); split2(v.z,h2,l2); split2(v.w,h3,l3);
    *(uint2*)(dh + i) = make_uint2(packbf(h0,h1), packbf(h2,h3));
    *(uint2*)(dl + i) = make_uint2(packbf(l0,l1), packbf(l2,l3));
}

// ---------------- expanded fp16-pair AND-mask build --------------------------
// For pair p in [0,1024): t = p>>5, t4 = (p>>3)&3, f = p&7; cols j0 = 64t+8f+2t4, j0+1.
__global__ void mask_prep(const int* __restrict__ seq_mask,
                          const int* __restrict__ sparse_masks) {
    int row = blockIdx.x;
    const int* s0 = seq_mask     + (size_t)0*SEQ*SEQ + (size_t)row*SEQ;
    const int* s1 = seq_mask     + (size_t)1*SEQ*SEQ + (size_t)row*SEQ;
    const int* p0 = sparse_masks + (size_t)0*SEQ*SEQ + (size_t)row*SEQ;
    const int* p1 = sparse_masks + (size_t)1*SEQ*SEQ + (size_t)row*SEQ;
    #pragma unroll
    for (int k = 0; k < 4; k++) {
        int p = threadIdx.x + k*256;
        int t = p >> 5, t4 = (p >> 3) & 3, f = p & 7;
        int j0 = t*64 + f*8 + t4*2;
        int2 a0 = *(const int2*)(s0 + j0);
        int2 a1 = *(const int2*)(s1 + j0);
        int2 b0 = *(const int2*)(p0 + j0);
        int2 b1 = *(const int2*)(p1 + j0);
        u32 m00 = ((a0.x & b0.x) ? 0xFFFFu : 0) | ((a0.y & b0.y) ? 0xFFFF0000u : 0);
        u32 m01 = ((a0.x & b1.x) ? 0xFFFFu : 0) | ((a0.y & b1.y) ? 0xFFFF0000u : 0);
        u32 m10 = ((a1.x & b0.x) ? 0xFFFFu : 0) | ((a1.y & b0.y) ? 0xFFFF0000u : 0);
        u32 m11 = ((a1.x & b1.x) ? 0xFFFFu : 0) | ((a1.y & b1.y) ? 0xFFFF0000u : 0);
        size_t base = (size_t)row*(SEQ/2) + p;
        g_maskex[(size_t)0*SEQ*(SEQ/2) + base] = m00;
        g_maskex[(size_t)1*SEQ*(SEQ/2) + base] = m01;
        g_maskex[(size_t)2*SEQ*(SEQ/2) + base] = m10;
        g_maskex[(size_t)3*SEQ*(SEQ/2) + base] = m11;
    }
}

// ---------------- split-bf16 GEMM (R6 config: 64x128 tile, k64, 2 buffers) --
// mode 0: A = x splits, B = QKV concat [1536][512]; epilogue -> gQ/gK/gV fp16.
// mode 1: A = O splits,  B = Wo [512][512];          epilogue -> fp32 out.
#define PJ_BUF 49152
__global__ __launch_bounds__(256, 2) void proj_gemm(float* __restrict__ Yout, int mode) {
    extern __shared__ char dsm[];
    u32 sb = (smem_u32(dsm) + 127) & ~127u;

    const __nv_bfloat16* A_h = mode ? gOh : gXh;
    const __nv_bfloat16* A_l = mode ? gOl : gXl;
    const __nv_bfloat16* B_h = mode ? gWh[3] : gWh[0];
    const __nv_bfloat16* B_l = mode ? gWl[3] : gWl[0];

    int tid = threadIdx.x, lane = tid & 31, warp = tid >> 5;
    int t4 = lane & 3, t8 = lane >> 2;
    int mrl = lane & 7, mm = lane >> 3;
    int wm = warp & 1, wn = warp >> 1;            // 2 x 4 warps, warp tile 32x32
    int m0 = blockIdx.x * 64, n0 = blockIdx.y * 128;

    #define PJ_ISSUE(c, buf) do { \
        _Pragma("unroll") \
        for (int q = 0; q < 12; q++) { \
            int idx = tid + q*256; \
            const __nv_bfloat16* s; u32 d; \
            if (idx < 1024) { \
                int mtx = idx >> 9, rem = idx & 511, r = rem >> 3, ch = rem & 7; \
                s = (mtx ? A_l : A_h) + (size_t)(m0 + r)*DIM + (c)*64 + ch*8; \
                d = sb + (buf)*PJ_BUF + mtx*8192 + r*128 + ((ch ^ (r & 7)) << 4); \
            } else { \
                int i2 = idx - 1024; \
                int mtx = i2 >> 10, rem = i2 & 1023, r = rem >> 3, ch = rem & 7; \
                s = (mtx ? B_l : B_h) + (size_t)(n0 + r)*DIM + (c)*64 + ch*8; \
                d = sb + (buf)*PJ_BUF + 16384 + mtx*16384 + r*128 + ((ch ^ (r & 7)) << 4); \
            } \
            CPA16(d, s); \
        } \
        CPCOMMIT(); \
    } while (0)

    float C[2][4][4];
    #pragma unroll
    for (int a = 0; a < 2; a++)
        #pragma unroll
        for (int b = 0; b < 4; b++)
            #pragma unroll
            for (int c = 0; c < 4; c++) C[a][b][c] = 0.f;

    PJ_ISSUE(0, 0);
    PJ_ISSUE(1, 1);

    for (int c = 0; c < 8; c++) {
        if (c < 7) CPWAIT(1); else CPWAIT(0);
        __syncthreads();
        u32 bb = sb + (c & 1)*PJ_BUF;

        #pragma unroll
        for (int ks = 0; ks < 4; ks++) {
            u32 AH[2][4], AL[2][4], BH[4][2], BL[4][2];
            int ch = 2*ks + (mm >> 1);
            #pragma unroll
            for (int fm = 0; fm < 2; fm++) {
                int row = wm*32 + fm*16 + (mm & 1)*8 + mrl;
                u32 a = bb + row*128 + ((ch ^ (row & 7)) << 4);
                LDM4(AH[fm][0], AH[fm][1], AH[fm][2], AH[fm][3], a);
                LDM4(AL[fm][0], AL[fm][1], AL[fm][2], AL[fm][3], a + 8192);
            }
            #pragma unroll
            for (int p = 0; p < 2; p++) {
                int row = wn*32 + p*16 + (mm & 1)*8 + mrl;
                u32 a = bb + 16384 + row*128 + ((ch ^ (row & 7)) << 4);
                LDM4(BH[2*p][0], BH[2*p+1][0], BH[2*p][1], BH[2*p+1][1], a);
                LDM4(BL[2*p][0], BL[2*p+1][0], BL[2*p][1], BL[2*p+1][1], a + 16384);
            }
            #pragma unroll
            for (int fm = 0; fm < 2; fm++)
                #pragma unroll
                for (int fn = 0; fn < 4; fn++) {
                    MMAB(C[fm][fn], AH[fm], BH[fn]);
                    MMAB(C[fm][fn], AH[fm], BL[fn]);
                    MMAB(C[fm][fn], AL[fm], BH[fn]);
                }
        }
        __syncthreads();
        if (c + 2 < 8) PJ_ISSUE(c + 2, c & 1);
    }

    #pragma unroll
    for (int fm = 0; fm < 2; fm++) {
        int rA = m0 + wm*32 + fm*16 + t8;
        #pragma unroll
        for (int fn = 0; fn < 4; fn++) {
            int n = n0 + wn*32 + fn*8 + 2*t4;
            float c0 = C[fm][fn][0], c1 = C[fm][fn][1];
            float c2 = C[fm][fn][2], c3 = C[fm][fn][3];
            if (mode) {
                *(float2*)(Yout + (size_t)rA*DIM + n)     = make_float2(c0, c1);
                *(float2*)(Yout + (size_t)(rA+8)*DIM + n) = make_float2(c2, c3);
            } else {
                int osel = n >> 9, col = n & 511;
                __half* dst = osel == 0 ? gQ : osel == 1 ? gK : gV;
                float sc = osel == 0 ? 0.125f * LOG2E : 1.f;
                *(u32*)(dst + (size_t)rA*DIM + col)     = cvtf16x2(c0*sc, c1*sc);
                *(u32*)(dst + (size_t)(rA+8)*DIM + col) = cvtf16x2(c2*sc, c3*sc);
            }
        }
    }
}

// ---------------- flash attention (fp16 mma, AND-masks, MMA row-sums) -------
// CTA: 128 i-rows of one (b,h); 8 warps x 16 rows; 32 j-tiles of 64.
// 3 stages, 1 sync/iter (issue-at-top into stage (t+2)%3).
#define AT_STG 16384   // per stage: K 8KB @0, V 8KB @8192
__global__ __launch_bounds__(256, 2) void attn_kernel() {
    extern __shared__ char dsm[];
    u32 sb = (smem_u32(dsm) + 127) & ~127u;

    int tid = threadIdx.x, lane = tid & 31, warp = tid >> 5;
    int t4 = lane & 3, t8 = lane >> 2;
    int mrl = lane & 7, mm = lane >> 3;
    int i0 = blockIdx.x * 128;
    int bh = blockIdx.y, b = bh >> 3, hh = bh & 7;
    int combo = b*2 + (hh & 1);

    #define AT_ISSUE(jt, st) do { \
        _Pragma("unroll") \
        for (int q = 0; q < 4; q++) { \
            int idx = tid + q*256; \
            int mtx = idx >> 9, rem = idx & 511, r = rem >> 3, ch = rem & 7; \
            const __half* s = (mtx ? gV : gK) + (size_t)(b*SEQ + (jt)*64 + r)*DIM + hh*DK + ch*8; \
            u32 d = sb + (st)*AT_STG + mtx*8192 + r*128 + ((ch ^ (r & 7)) << 4); \
            CPA16(d, s); \
        } \
        CPCOMMIT(); \
    } while (0)

    AT_ISSUE(0, 0);
    AT_ISSUE(1, 1);

    // Q fragments (fp16) held in registers for the whole kernel
    u32 QA[4][4];
    {
        size_t qbase = (size_t)(b*SEQ + i0 + warp*16 + t8)*DIM + hh*DK + 2*t4;
        #pragma unroll
        for (int ks = 0; ks < 4; ks++) {
            QA[ks][0] = *(const u32*)(gQ + qbase + ks*16);
            QA[ks][1] = *(const u32*)(gQ + qbase + ks*16 + 8*DIM);
            QA[ks][2] = *(const u32*)(gQ + qbase + ks*16 + 8);
            QA[ks][3] = *(const u32*)(gQ + qbase + ks*16 + 8*DIM + 8);
        }
    }

    // expanded masks: [combo][row][tile][t4][f]
    const u32* mexA = g_maskex + ((size_t)combo*SEQ + (i0 + warp*16 + t8))*(SEQ/2) + t4*8;
    const u32* mexB = mexA + 8*(SEQ/2);

    float O[8][4];
    #pragma unroll
    for (int f = 0; f < 8; f++)
        #pragma unroll
        for (int c = 0; c < 4; c++) O[f][c] = 0.f;
    float LS[4] = {0.f, 0.f, 0.f, 0.f};     // MMA row-sums: LS[0]=rowA, LS[2]=rowB

    for (int t = 0; t < 32; t++) {
        if (t < 31) CPWAIT(1); else CPWAIT(0);
        __syncthreads();
        if (t + 2 < 32) AT_ISSUE(t + 2, (t + 2) % 3);
        u32 kb = sb + (t % 3)*AT_STG;
        u32 vb = kb + 8192;

        // AND-mask words for this tile (LDG hidden under MMAs)
        uint4 mA0 = *(const uint4*)(mexA + t*32);
        uint4 mA1 = *(const uint4*)(mexA + t*32 + 4);
        uint4 mB0 = *(const uint4*)(mexB + t*32);
        uint4 mB1 = *(const uint4*)(mexB + t*32 + 4);
        u32 MA[8] = {mA0.x, mA0.y, mA0.z, mA0.w, mA1.x, mA1.y, mA1.z, mA1.w};
        u32 MB[8] = {mB0.x, mB0.y, mB0.z, mB0.w, mB1.x, mB1.y, mB1.z, mB1.w};

        // S = Q K^T
        float S[8][4];
        #pragma unroll
        for (int f = 0; f < 8; f++)
            #pragma unroll
            for (int c = 0; c < 4; c++) S[f][c] = 0.f;

        #pragma unroll
        for (int ks = 0; ks < 4; ks++) {
            u32 BH[8][2];
            int ch = 2*ks + (mm >> 1);
            #pragma unroll
            for (int p = 0; p < 4; p++) {
                int row = 16*p + (mm & 1)*8 + mrl;
                u32 a = kb + row*128 + ((ch ^ (row & 7)) << 4);
                LDM4(BH[2*p][0], BH[2*p+1][0], BH[2*p][1], BH[2*p+1][1], a);
            }
            #pragma unroll
            for (int f = 0; f < 8; f++) MMAH(S[f], QA[ks], BH[f]);
        }

        // ex2 + fp16 pack + AND-mask (no selects, no shifts, no scalar sums)
        u32 PH[4][4];
        #pragma unroll
        for (int f = 0; f < 8; f++) {
            float p0 = ex2f(S[f][0]);
            float p1 = ex2f(S[f][1]);
            float p2 = ex2f(S[f][2]);
            float p3 = ex2f(S[f][3]);
            int ks = f >> 1, o = (f & 1)*2;
            PH[ks][o]   = cvtf16x2(p0, p1) & MA[f];
            PH[ks][o+1] = cvtf16x2(p2, p3) & MB[f];
        }

        // O += P V; LS += P @ ones (row sums on the tensor pipe)
        #pragma unroll
        for (int ks = 0; ks < 4; ks++) {
            u32 VH[8][2];
            int row = 16*ks + (mm >> 1)*8 + mrl;
            #pragma unroll
            for (int p = 0; p < 4; p++) {
                int ch = 2*p + (mm & 1);
                u32 a = vb + row*128 + ((ch ^ (row & 7)) << 4);
                LDM4T(VH[2*p][0], VH[2*p+1][0], VH[2*p][1], VH[2*p+1][1], a);
            }
            #pragma unroll
            for (int f = 0; f < 8; f++) MMAH(O[f], PH[ks], VH[f]);
            MMAH2(LS, PH[ks], ONESF16, ONESF16);
        }
    }

    float invA = (LS[0] > 0.f) ? 1.0f / LS[0] : 0.f;
    float invB = (LS[2] > 0.f) ? 1.0f / LS[2] : 0.f;

    size_t obase = (size_t)(b*SEQ + i0 + warp*16 + t8)*DIM + hh*DK + 2*t4;
    #pragma unroll
    for (int f = 0; f < 8; f++) {
        float o0 = O[f][0]*invA, o1 = O[f][1]*invA;
        float o2 = O[f][2]*invB, o3 = O[f][3]*invB;
        __nv_bfloat16 h0,l0,h1,l1,h2,l2,h3,l3;
        split2(o0,h0,l0); split2(o1,h1,l1); split2(o2,h2,l2); split2(o3,h3,l3);
        *(u32*)(gOh + obase + 8*f)         = packbf(h0, h1);
        *(u32*)(gOl + obase + 8*f)         = packbf(l0, l1);
        *(u32*)(gOh + obase + 8*f + 8*DIM) = packbf(h2, h3);
        *(u32*)(gOl + obase + 8*f + 8*DIM) = packbf(l2, l3);
    }
}

// ---------------------------------------------------------------------------
extern "C" void kernel_launch(void* const* d_in, const int* in_sizes, int n_in,
                              void* d_out, int out_size)
{
    const float* x  = (const float*)d_in[0];
    const float* Wq = (const float*)d_in[1];
    const float* Wk = (const float*)d_in[2];
    const float* Wv = (const float*)d_in[3];
    const float* Wo = (const float*)d_in[4];
    const int* seq_mask     = (const int*)d_in[5];
    const int* sparse_masks = (const int*)d_in[6];
    float* out = (float*)d_out;

    cudaFuncSetAttribute(proj_gemm,   cudaFuncAttributeMaxDynamicSharedMemorySize, 2*PJ_BUF);
    cudaFuncSetAttribute(attn_kernel, cudaFuncAttributeMaxDynamicSharedMemorySize, 3*AT_STG);

    mask_prep<<<SEQ, 256>>>(seq_mask, sparse_masks);
    conv_all<<<2048 + 4*256, 256>>>(x, Wq, Wk, Wv, Wo);

    proj_gemm<<<dim3(MT/64, 1536/128), 256, 2*PJ_BUF>>>(nullptr, 0); // fused QKV
    attn_kernel<<<dim3(SEQ/128, BATCH*NHEAD), 256, 3*AT_STG>>>();
    proj_gemm<<<dim3(MT/64, DIM/128), 256, 2*PJ_BUF>>>(out, 1);      // O @ Wo^T
    (void)in_sizes; (void)n_in; (void)out_size;
}

// round 10
// speedup vs baseline: 1.3833x; 1.3833x over previous
#include <cuda_runtime.h>
#include <cuda_bf16.h>
#include <cuda_fp16.h>
#include <math.h>

typedef unsigned int u32;
typedef unsigned long long u64;

#define BATCH 2
#define SEQ   2048
#define DIM   512
#define NHEAD 8
#define DK    64
#define MT    (BATCH*SEQ)
#define LOG2E 1.4426950408889634f
#define ONESF16 0x3C003C00u

// ---------------- global scratch (alloc-free) ------------------------------
__device__ __nv_bfloat16 gXh[MT*DIM], gXl[MT*DIM];
__device__ __nv_bfloat16 gWh[4][DIM*DIM], gWl[4][DIM*DIM];  // 0..2 = QKV (contig), 3 = O
__device__ __half gQ[MT*DIM];                // pre-scaled 0.125*log2e
__device__ __half gK[MT*DIM];
__device__ __half gV[MT*DIM];
__device__ __nv_bfloat16 gOh[MT*DIM], gOl[MT*DIM];
__device__ u32 g_mask[4*SEQ*(SEQ/32)];       // [b*2+par][row][word]  (compact bits)

// ---------------- helpers ---------------------------------------------------
static __device__ __forceinline__ u32 smem_u32(const void* p) {
    u32 a; asm("{ .reg .u64 t; cvta.to.shared.u64 t, %1; cvt.u32.u64 %0, t; }" : "=r"(a) : "l"(p));
    return a;
}
static __device__ __forceinline__ float ex2f(float x) {
    float y; asm("ex2.approx.f32 %0, %1;" : "=f"(y) : "f"(x)); return y;
}
static __device__ __forceinline__ void split2(float v, __nv_bfloat16& hi, __nv_bfloat16& lo) {
    hi = __float2bfloat16(v);
    lo = __float2bfloat16(v - __bfloat162float(hi));
}
static __device__ __forceinline__ u32 packbf(__nv_bfloat16 a, __nv_bfloat16 b) {
    return (u32)__bfloat16_as_ushort(a) | ((u32)__bfloat16_as_ushort(b) << 16);
}
// packs {lo, hi} halves
static __device__ __forceinline__ u32 cvtf16x2(float lo, float hi) {
    u32 d; asm("cvt.rn.f16x2.f32 %0, %1, %2;" : "=r"(d) : "f"(hi), "f"(lo)); return d;
}

#define LDM4(r0,r1,r2,r3,a) \
    asm volatile("ldmatrix.sync.aligned.m8n8.x4.shared.b16 {%0,%1,%2,%3}, [%4];" \
        : "=r"(r0),"=r"(r1),"=r"(r2),"=r"(r3) : "r"(a))
#define LDM4T(r0,r1,r2,r3,a) \
    asm volatile("ldmatrix.sync.aligned.m8n8.x4.trans.shared.b16 {%0,%1,%2,%3}, [%4];" \
        : "=r"(r0),"=r"(r1),"=r"(r2),"=r"(r3) : "r"(a))
#define MMAB(d,a,b) \
    asm volatile("mma.sync.aligned.m16n8k16.row.col.f32.bf16.bf16.f32 " \
        "{%0,%1,%2,%3}, {%4,%5,%6,%7}, {%8,%9}, {%0,%1,%2,%3};" \
        : "+f"((d)[0]),"+f"((d)[1]),"+f"((d)[2]),"+f"((d)[3]) \
        : "r"((a)[0]),"r"((a)[1]),"r"((a)[2]),"r"((a)[3]),"r"((b)[0]),"r"((b)[1]))
#define MMAH(d,a,b) \
    asm volatile("mma.sync.aligned.m16n8k16.row.col.f32.f16.f16.f32 " \
        "{%0,%1,%2,%3}, {%4,%5,%6,%7}, {%8,%9}, {%0,%1,%2,%3};" \
        : "+f"((d)[0]),"+f"((d)[1]),"+f"((d)[2]),"+f"((d)[3]) \
        : "r"((a)[0]),"r"((a)[1]),"r"((a)[2]),"r"((a)[3]),"r"((b)[0]),"r"((b)[1]))
#define MMAH2(d,a,b0,b1) \
    asm volatile("mma.sync.aligned.m16n8k16.row.col.f32.f16.f16.f32 " \
        "{%0,%1,%2,%3}, {%4,%5,%6,%7}, {%8,%9}, {%0,%1,%2,%3};" \
        : "+f"((d)[0]),"+f"((d)[1]),"+f"((d)[2]),"+f"((d)[3]) \
        : "r"((a)[0]),"r"((a)[1]),"r"((a)[2]),"r"((a)[3]),"r"(b0),"r"(b1))

#define CPA16(d, s) asm volatile("cp.async.cg.shared.global [%0], [%1], 16;" :: "r"(d), "l"(s) : "memory")
#define CPCOMMIT()  asm volatile("cp.async.commit_group;" ::: "memory")
#define CPWAIT(n)   asm volatile("cp.async.wait_group %0;" :: "n"(n) : "memory")

// ---------------- fp32 -> (hi, lo) bf16 split: x + all weights, one launch --
__global__ void conv_all(const float* __restrict__ x,
                         const float* __restrict__ Wq, const float* __restrict__ Wk,
                         const float* __restrict__ Wv, const float* __restrict__ Wo) {
    int blk = blockIdx.x;
    const float* src;
    __nv_bfloat16 *dh, *dl;
    int i;
    if (blk < 2048) {                      // x: 2M elements
        src = x; dh = gXh; dl = gXl;
        i = (blk * 256 + threadIdx.x) * 4;
    } else {                               // weights: 256 blocks each
        int sel = (blk - 2048) >> 8, b2 = (blk - 2048) & 255;
        src = sel == 0 ? Wq : sel == 1 ? Wk : sel == 2 ? Wv : Wo;
        dh = gWh[sel]; dl = gWl[sel];
        i = (b2 * 256 + threadIdx.x) * 4;
    }
    float4 v = *(const float4*)(src + i);
    __nv_bfloat16 h0,l0,h1,l1,h2,l2,h3,l3;
    split2(v.x,h0,l0); split2(v.y,h1,l1); split2(v.z,h2,l2); split2(v.w,h3,l3);
    *(uint2*)(dh + i) = make_uint2(packbf(h0,h1), packbf(h2,h3));
    *(uint2*)(dl + i) = make_uint2(packbf(l0,l1), packbf(l2,l3));
}

// ---------------- combined masks -> compact bit tables (batched loads) ------
__global__ void mask_prep(const int* __restrict__ seq_mask,
                          const int* __restrict__ sparse_masks) {
    int row  = blockIdx.x;
    int warp = threadIdx.x >> 5, lane = threadIdx.x & 31;
    const int* s0 = seq_mask     + (size_t)0*SEQ*SEQ + (size_t)row*SEQ;
    const int* s1 = seq_mask     + (size_t)1*SEQ*SEQ + (size_t)row*SEQ;
    const int* p0 = sparse_masks + (size_t)0*SEQ*SEQ + (size_t)row*SEQ;
    const int* p1 = sparse_masks + (size_t)1*SEQ*SEQ + (size_t)row*SEQ;
    int a0[8], a1[8], b0[8], b1[8];
    #pragma unroll
    for (int q = 0; q < 8; q++) {
        int j = (warp*8 + q)*32 + lane;
        a0[q] = s0[j]; a1[q] = s1[j]; b0[q] = p0[j]; b1[q] = p1[j];
    }
    #pragma unroll
    for (int q = 0; q < 8; q++) {
        int w = warp*8 + q;
        u32 m00 = __ballot_sync(0xffffffffu, (a0[q] & b0[q]) != 0);
        u32 m01 = __ballot_sync(0xffffffffu, (a0[q] & b1[q]) != 0);
        u32 m10 = __ballot_sync(0xffffffffu, (a1[q] & b0[q]) != 0);
        u32 m11 = __ballot_sync(0xffffffffu, (a1[q] & b1[q]) != 0);
        if (lane == 0) {
            g_mask[((size_t)0*SEQ + row)*(SEQ/32) + w] = m00;
            g_mask[((size_t)1*SEQ + row)*(SEQ/32) + w] = m01;
            g_mask[((size_t)2*SEQ + row)*(SEQ/32) + w] = m10;
            g_mask[((size_t)3*SEQ + row)*(SEQ/32) + w] = m11;
        }
    }
}

// ---------------- split-bf16 GEMM (R6 config: 64x128 tile, k64, 2 buffers) --
// mode 0: A = x splits, B = QKV concat [1536][512]; epilogue -> gQ/gK/gV fp16.
// mode 1: A = O splits,  B = Wo [512][512];          epilogue -> fp32 out.
#define PJ_BUF 49152
__global__ __launch_bounds__(256, 2) void proj_gemm(float* __restrict__ Yout, int mode) {
    extern __shared__ char dsm[];
    u32 sb = (smem_u32(dsm) + 127) & ~127u;

    const __nv_bfloat16* A_h = mode ? gOh : gXh;
    const __nv_bfloat16* A_l = mode ? gOl : gXl;
    const __nv_bfloat16* B_h = mode ? gWh[3] : gWh[0];
    const __nv_bfloat16* B_l = mode ? gWl[3] : gWl[0];

    int tid = threadIdx.x, lane = tid & 31, warp = tid >> 5;
    int t4 = lane & 3, t8 = lane >> 2;
    int mrl = lane & 7, mm = lane >> 3;
    int wm = warp & 1, wn = warp >> 1;            // 2 x 4 warps, warp tile 32x32
    int m0 = blockIdx.x * 64, n0 = blockIdx.y * 128;

    #define PJ_ISSUE(c, buf) do { \
        _Pragma("unroll") \
        for (int q = 0; q < 12; q++) { \
            int idx = tid + q*256; \
            const __nv_bfloat16* s; u32 d; \
            if (idx < 1024) { \
                int mtx = idx >> 9, rem = idx & 511, r = rem >> 3, ch = rem & 7; \
                s = (mtx ? A_l : A_h) + (size_t)(m0 + r)*DIM + (c)*64 + ch*8; \
                d = sb + (buf)*PJ_BUF + mtx*8192 + r*128 + ((ch ^ (r & 7)) << 4); \
            } else { \
                int i2 = idx - 1024; \
                int mtx = i2 >> 10, rem = i2 & 1023, r = rem >> 3, ch = rem & 7; \
                s = (mtx ? B_l : B_h) + (size_t)(n0 + r)*DIM + (c)*64 + ch*8; \
                d = sb + (buf)*PJ_BUF + 16384 + mtx*16384 + r*128 + ((ch ^ (r & 7)) << 4); \
            } \
            CPA16(d, s); \
        } \
        CPCOMMIT(); \
    } while (0)

    float C[2][4][4];
    #pragma unroll
    for (int a = 0; a < 2; a++)
        #pragma unroll
        for (int b = 0; b < 4; b++)
            #pragma unroll
            for (int c = 0; c < 4; c++) C[a][b][c] = 0.f;

    PJ_ISSUE(0, 0);
    PJ_ISSUE(1, 1);

    for (int c = 0; c < 8; c++) {
        if (c < 7) CPWAIT(1); else CPWAIT(0);
        __syncthreads();
        u32 bb = sb + (c & 1)*PJ_BUF;

        #pragma unroll
        for (int ks = 0; ks < 4; ks++) {
            u32 AH[2][4], AL[2][4], BH[4][2], BL[4][2];
            int ch = 2*ks + (mm >> 1);
            #pragma unroll
            for (int fm = 0; fm < 2; fm++) {
                int row = wm*32 + fm*16 + (mm & 1)*8 + mrl;
                u32 a = bb + row*128 + ((ch ^ (row & 7)) << 4);
                LDM4(AH[fm][0], AH[fm][1], AH[fm][2], AH[fm][3], a);
                LDM4(AL[fm][0], AL[fm][1], AL[fm][2], AL[fm][3], a + 8192);
            }
            #pragma unroll
            for (int p = 0; p < 2; p++) {
                int row = wn*32 + p*16 + (mm & 1)*8 + mrl;
                u32 a = bb + 16384 + row*128 + ((ch ^ (row & 7)) << 4);
                LDM4(BH[2*p][0], BH[2*p+1][0], BH[2*p][1], BH[2*p+1][1], a);
                LDM4(BL[2*p][0], BL[2*p+1][0], BL[2*p][1], BL[2*p+1][1], a + 16384);
            }
            #pragma unroll
            for (int fm = 0; fm < 2; fm++)
                #pragma unroll
                for (int fn = 0; fn < 4; fn++) {
                    MMAB(C[fm][fn], AH[fm], BH[fn]);
                    MMAB(C[fm][fn], AH[fm], BL[fn]);
                    MMAB(C[fm][fn], AL[fm], BH[fn]);
                }
        }
        __syncthreads();
        if (c + 2 < 8) PJ_ISSUE(c + 2, c & 1);
    }

    #pragma unroll
    for (int fm = 0; fm < 2; fm++) {
        int rA = m0 + wm*32 + fm*16 + t8;
        #pragma unroll
        for (int fn = 0; fn < 4; fn++) {
            int n = n0 + wn*32 + fn*8 + 2*t4;
            float c0 = C[fm][fn][0], c1 = C[fm][fn][1];
            float c2 = C[fm][fn][2], c3 = C[fm][fn][3];
            if (mode) {
                *(float2*)(Yout + (size_t)rA*DIM + n)     = make_float2(c0, c1);
                *(float2*)(Yout + (size_t)(rA+8)*DIM + n) = make_float2(c2, c3);
            } else {
                int osel = n >> 9, col = n & 511;
                __half* dst = osel == 0 ? gQ : osel == 1 ? gK : gV;
                float sc = osel == 0 ? 0.125f * LOG2E : 1.f;
                *(u32*)(dst + (size_t)rA*DIM + col)     = cvtf16x2(c0*sc, c1*sc);
                *(u32*)(dst + (size_t)(rA+8)*DIM + col) = cvtf16x2(c2*sc, c3*sc);
            }
        }
    }
}

// ---------------- flash attention (fp16 mma, 3-stage, 1 sync/iter) ----------
// CTA: 128 i-rows of one (b,h); 8 warps x 16 rows; 32 j-tiles of 64.
// Compact bitmasks; row sums via P @ ones on the tensor pipe.
#define AT_STG 16384   // per stage: K 8KB @0, V 8KB @8192
__global__ __launch_bounds__(256, 2) void attn_kernel() {
    extern __shared__ char dsm[];
    u32 sb = (smem_u32(dsm) + 127) & ~127u;

    int tid = threadIdx.x, lane = tid & 31, warp = tid >> 5;
    int t4 = lane & 3, t8 = lane >> 2;
    int mrl = lane & 7, mm = lane >> 3;
    int i0 = blockIdx.x * 128;
    int bh = blockIdx.y, b = bh >> 3, hh = bh & 7;
    int combo = b*2 + (hh & 1);

    #define AT_ISSUE(jt, st) do { \
        _Pragma("unroll") \
        for (int q = 0; q < 4; q++) { \
            int idx = tid + q*256; \
            int mtx = idx >> 9, rem = idx & 511, r = rem >> 3, ch = rem & 7; \
            const __half* s = (mtx ? gV : gK) + (size_t)(b*SEQ + (jt)*64 + r)*DIM + hh*DK + ch*8; \
            u32 d = sb + (st)*AT_STG + mtx*8192 + r*128 + ((ch ^ (r & 7)) << 4); \
            CPA16(d, s); \
        } \
        CPCOMMIT(); \
    } while (0)

    AT_ISSUE(0, 0);
    AT_ISSUE(1, 1);

    // Q fragments (fp16) held in registers for the whole kernel
    u32 QA[4][4];
    {
        size_t qbase = (size_t)(b*SEQ + i0 + warp*16 + t8)*DIM + hh*DK + 2*t4;
        #pragma unroll
        for (int ks = 0; ks < 4; ks++) {
            QA[ks][0] = *(const u32*)(gQ + qbase + ks*16);
            QA[ks][1] = *(const u32*)(gQ + qbase + ks*16 + 8*DIM);
            QA[ks][2] = *(const u32*)(gQ + qbase + ks*16 + 8);
            QA[ks][3] = *(const u32*)(gQ + qbase + ks*16 + 8*DIM + 8);
        }
    }

    const u32* mrowA = g_mask + ((size_t)combo*SEQ + i0 + warp*16 + t8)*(SEQ/32);
    const u32* mrowB = mrowA + 8*(SEQ/32);

    float O[8][4];
    #pragma unroll
    for (int f = 0; f < 8; f++)
        #pragma unroll
        for (int c = 0; c < 4; c++) O[f][c] = 0.f;
    float LS[4] = {0.f, 0.f, 0.f, 0.f};     // tensor-core row sums: LS[0]=rowA, LS[2]=rowB

    for (int t = 0; t < 32; t++) {
        if (t < 31) CPWAIT(1); else CPWAIT(0);
        __syncthreads();
        if (t + 2 < 32) AT_ISSUE(t + 2, (t + 2) % 3);
        u32 kb = sb + (t % 3)*AT_STG;
        u32 vb = kb + 8192;

        // mask words early (LDG hidden under S MMAs)
        uint2 wA = *(const uint2*)(mrowA + (t << 1));
        uint2 wB = *(const uint2*)(mrowB + (t << 1));

        // S = Q K^T
        float S[8][4];
        #pragma unroll
        for (int f = 0; f < 8; f++)
            #pragma unroll
            for (int c = 0; c < 4; c++) S[f][c] = 0.f;

        #pragma unroll
        for (int ks = 0; ks < 4; ks++) {
            u32 BH[8][2];
            int ch = 2*ks + (mm >> 1);
            #pragma unroll
            for (int p = 0; p < 4; p++) {
                int row = 16*p + (mm & 1)*8 + mrl;
                u32 a = kb + row*128 + ((ch ^ (row & 7)) << 4);
                LDM4(BH[2*p][0], BH[2*p+1][0], BH[2*p][1], BH[2*p+1][1], a);
            }
            #pragma unroll
            for (int f = 0; f < 8; f++) MMAH(S[f], QA[ks], BH[f]);
        }

        // mask + ex2 + pack P to fp16 A-fragments (registers only)
        u64 mwA = (u64)wA.x | ((u64)wA.y << 32);
        u64 mwB = (u64)wB.x | ((u64)wB.y << 32);

        u32 PH[4][4];
        #pragma unroll
        for (int f = 0; f < 8; f++) {
            int sh = 8*f + 2*t4;
            u32 bA = (u32)(mwA >> sh);
            u32 bB = (u32)(mwB >> sh);
            float p0 = (bA & 1u) ? ex2f(S[f][0]) : 0.f;
            float p1 = (bA & 2u) ? ex2f(S[f][1]) : 0.f;
            float p2 = (bB & 1u) ? ex2f(S[f][2]) : 0.f;
            float p3 = (bB & 2u) ? ex2f(S[f][3]) : 0.f;
            int ks = f >> 1, o = (f & 1)*2;
            PH[ks][o]   = cvtf16x2(p0, p1);
            PH[ks][o+1] = cvtf16x2(p2, p3);
        }

        // O += P V; LS += P @ ones (row sums on the tensor pipe)
        #pragma unroll
        for (int ks = 0; ks < 4; ks++) {
            u32 VH[8][2];
            int row = 16*ks + (mm >> 1)*8 + mrl;
            #pragma unroll
            for (int p = 0; p < 4; p++) {
                int ch = 2*p + (mm & 1);
                u32 a = vb + row*128 + ((ch ^ (row & 7)) << 4);
                LDM4T(VH[2*p][0], VH[2*p+1][0], VH[2*p][1], VH[2*p+1][1], a);
            }
            #pragma unroll
            for (int f = 0; f < 8; f++) MMAH(O[f], PH[ks], VH[f]);
            MMAH2(LS, PH[ks], ONESF16, ONESF16);
        }
    }

    float invA = (LS[0] > 0.f) ? 1.0f / LS[0] : 0.f;
    float invB = (LS[2] > 0.f) ? 1.0f / LS[2] : 0.f;

    size_t obase = (size_t)(b*SEQ + i0 + warp*16 + t8)*DIM + hh*DK + 2*t4;
    #pragma unroll
    for (int f = 0; f < 8; f++) {
        float o0 = O[f][0]*invA, o1 = O[f][1]*invA;
        float o2 = O[f][2]*invB, o3 = O[f][3]*invB;
        __nv_bfloat16 h0,l0,h1,l1,h2,l2,h3,l3;
        split2(o0,h0,l0); split2(o1,h1,l1); split2(o2,h2,l2); split2(o3,h3,l3);
        *(u32*)(gOh + obase + 8*f)         = packbf(h0, h1);
        *(u32*)(gOl + obase + 8*f)         = packbf(l0, l1);
        *(u32*)(gOh + obase + 8*f + 8*DIM) = packbf(h2, h3);
        *(u32*)(gOl + obase + 8*f + 8*DIM) = packbf(l2, l3);
    }
}

// ---------------------------------------------------------------------------
extern "C" void kernel_launch(void* const* d_in, const int* in_sizes, int n_in,
                              void* d_out, int out_size)
{
    const float* x  = (const float*)d_in[0];
    const float* Wq = (const float*)d_in[1];
    const float* Wk = (const float*)d_in[2];
    const float* Wv = (const float*)d_in[3];
    const float* Wo = (const float*)d_in[4];
    const int* seq_mask     = (const int*)d_in[5];
    const int* sparse_masks = (const int*)d_in[6];
    float* out = (float*)d_out;

    cudaFuncSetAttribute(proj_gemm,   cudaFuncAttributeMaxDynamicSharedMemorySize, 2*PJ_BUF);
    cudaFuncSetAttribute(attn_kernel, cudaFuncAttributeMaxDynamicSharedMemorySize, 3*AT_STG);

    mask_prep<<<SEQ, 256>>>(seq_mask, sparse_masks);
    conv_all<<<2048 + 4*256, 256>>>(x, Wq, Wk, Wv, Wo);

    proj_gemm<<<dim3(MT/64, 1536/128), 256, 2*PJ_BUF>>>(nullptr, 0); // fused QKV
    attn_kernel<<<dim3(SEQ/128, BATCH*NHEAD), 256, 3*AT_STG>>>();
    proj_gemm<<<dim3(MT/64, DIM/128), 256, 2*PJ_BUF>>>(out, 1);      // O @ Wo^T
    (void)in_sizes; (void)n_in; (void)out_size;
}

// round 11
// speedup vs baseline: 1.7123x; 1.2379x over previous
#include <cuda_runtime.h>
#include <cuda_bf16.h>
#include <cuda_fp16.h>
#include <math.h>

typedef unsigned int u32;
typedef unsigned long long u64;

#define BATCH 2
#define SEQ   2048
#define DIM   512
#define NHEAD 8
#define DK    64
#define MT    (BATCH*SEQ)
#define LOG2E 1.4426950408889634f
#define ONESF16 0x3C003C00u
#define WSCALE 64.0f
#define INVWS  (1.0f/64.0f)

// ---------------- global scratch (alloc-free) ------------------------------
__device__ __half gXf[MT*DIM];                   // x as fp16
__device__ __half gWh[4][DIM*DIM], gWl[4][DIM*DIM];  // W*64 fp16 hi/lo; 0..2 QKV contig, 3 = O
__device__ __half gQ[MT*DIM];                    // pre-scaled 0.125*log2e
__device__ __half gK[MT*DIM];
__device__ __half gV[MT*DIM];
__device__ __half gO[MT*DIM];                    // attn output, fp16
__device__ u32 g_mask[4*SEQ*(SEQ/32)];           // [b*2+par][row][word] compact bits

// ---------------- helpers ---------------------------------------------------
static __device__ __forceinline__ u32 smem_u32(const void* p) {
    u32 a; asm("{ .reg .u64 t; cvta.to.shared.u64 t, %1; cvt.u32.u64 %0, t; }" : "=r"(a) : "l"(p));
    return a;
}
static __device__ __forceinline__ float ex2f(float x) {
    float y; asm("ex2.approx.f32 %0, %1;" : "=f"(y) : "f"(x)); return y;
}
static __device__ __forceinline__ void splith(float v, __half& hi, __half& lo) {
    hi = __float2half_rn(v);
    lo = __float2half_rn(v - __half2float(hi));
}
static __device__ __forceinline__ u32 packh(__half a, __half b) {
    return (u32)__half_as_ushort(a) | ((u32)__half_as_ushort(b) << 16);
}
// packs {lo, hi} halves
static __device__ __forceinline__ u32 cvtf16x2(float lo, float hi) {
    u32 d; asm("cvt.rn.f16x2.f32 %0, %1, %2;" : "=r"(d) : "f"(hi), "f"(lo)); return d;
}
static __device__ __forceinline__ u32 prmt0(u32 a, u32 sel) {
    u32 d; asm("prmt.b32 %0, %1, %2, %3;" : "=r"(d) : "r"(a), "r"(0u), "r"(sel)); return d;
}

#define LDM4(r0,r1,r2,r3,a) \
    asm volatile("ldmatrix.sync.aligned.m8n8.x4.shared.b16 {%0,%1,%2,%3}, [%4];" \
        : "=r"(r0),"=r"(r1),"=r"(r2),"=r"(r3) : "r"(a))
#define LDM4T(r0,r1,r2,r3,a) \
    asm volatile("ldmatrix.sync.aligned.m8n8.x4.trans.shared.b16 {%0,%1,%2,%3}, [%4];" \
        : "=r"(r0),"=r"(r1),"=r"(r2),"=r"(r3) : "r"(a))
#define MMAH(d,a,b) \
    asm volatile("mma.sync.aligned.m16n8k16.row.col.f32.f16.f16.f32 " \
        "{%0,%1,%2,%3}, {%4,%5,%6,%7}, {%8,%9}, {%0,%1,%2,%3};" \
        : "+f"((d)[0]),"+f"((d)[1]),"+f"((d)[2]),"+f"((d)[3]) \
        : "r"((a)[0]),"r"((a)[1]),"r"((a)[2]),"r"((a)[3]),"r"((b)[0]),"r"((b)[1]))
#define MMAH2(d,a,b0,b1) \
    asm volatile("mma.sync.aligned.m16n8k16.row.col.f32.f16.f16.f32 " \
        "{%0,%1,%2,%3}, {%4,%5,%6,%7}, {%8,%9}, {%0,%1,%2,%3};" \
        : "+f"((d)[0]),"+f"((d)[1]),"+f"((d)[2]),"+f"((d)[3]) \
        : "r"((a)[0]),"r"((a)[1]),"r"((a)[2]),"r"((a)[3]),"r"(b0),"r"(b1))

#define CPA16(d, s) asm volatile("cp.async.cg.shared.global [%0], [%1], 16;" :: "r"(d), "l"(s) : "memory")
#define CPCOMMIT()  asm volatile("cp.async.commit_group;" ::: "memory")
#define CPWAIT(n)   asm volatile("cp.async.wait_group %0;" :: "n"(n) : "memory")

// ---------------- conversions: x -> fp16; W*64 -> fp16 hi/lo ----------------
__global__ void conv_all(const float* __restrict__ x,
                         const float* __restrict__ Wq, const float* __restrict__ Wk,
                         const float* __restrict__ Wv, const float* __restrict__ Wo) {
    int blk = blockIdx.x;
    if (blk < 2048) {                      // x: 2M elements, single fp16
        int i = (blk * 256 + threadIdx.x) * 4;
        float4 v = *(const float4*)(x + i);
        *(uint2*)(gXf + i) = make_uint2(cvtf16x2(v.x, v.y), cvtf16x2(v.z, v.w));
    } else {                               // weights: 256 blocks each, *64 hi/lo
        int sel = (blk - 2048) >> 8, b2 = (blk - 2048) & 255;
        const float* src = sel == 0 ? Wq : sel == 1 ? Wk : sel == 2 ? Wv : Wo;
        int i = (b2 * 256 + threadIdx.x) * 4;
        float4 v = *(const float4*)(src + i);
        __half h0,l0,h1,l1,h2,l2,h3,l3;
        splith(v.x*WSCALE,h0,l0); splith(v.y*WSCALE,h1,l1);
        splith(v.z*WSCALE,h2,l2); splith(v.w*WSCALE,h3,l3);
        *(uint2*)(gWh[sel] + i) = make_uint2(packh(h0,h1), packh(h2,h3));
        *(uint2*)(gWl[sel] + i) = make_uint2(packh(l0,l1), packh(l2,l3));
    }
}

// ---------------- combined masks -> compact bit tables (batched loads) ------
__global__ void mask_prep(const int* __restrict__ seq_mask,
                          const int* __restrict__ sparse_masks) {
    int row  = blockIdx.x;
    int warp = threadIdx.x >> 5, lane = threadIdx.x & 31;
    const int* s0 = seq_mask     + (size_t)0*SEQ*SEQ + (size_t)row*SEQ;
    const int* s1 = seq_mask     + (size_t)1*SEQ*SEQ + (size_t)row*SEQ;
    const int* p0 = sparse_masks + (size_t)0*SEQ*SEQ + (size_t)row*SEQ;
    const int* p1 = sparse_masks + (size_t)1*SEQ*SEQ + (size_t)row*SEQ;
    int a0[8], a1[8], b0[8], b1[8];
    #pragma unroll
    for (int q = 0; q < 8; q++) {
        int j = (warp*8 + q)*32 + lane;
        a0[q] = s0[j]; a1[q] = s1[j]; b0[q] = p0[j]; b1[q] = p1[j];
    }
    #pragma unroll
    for (int q = 0; q < 8; q++) {
        int w = warp*8 + q;
        u32 m00 = __ballot_sync(0xffffffffu, (a0[q] & b0[q]) != 0);
        u32 m01 = __ballot_sync(0xffffffffu, (a0[q] & b1[q]) != 0);
        u32 m10 = __ballot_sync(0xffffffffu, (a1[q] & b0[q]) != 0);
        u32 m11 = __ballot_sync(0xffffffffu, (a1[q] & b1[q]) != 0);
        if (lane == 0) {
            g_mask[((size_t)0*SEQ + row)*(SEQ/32) + w] = m00;
            g_mask[((size_t)1*SEQ + row)*(SEQ/32) + w] = m01;
            g_mask[((size_t)2*SEQ + row)*(SEQ/32) + w] = m10;
            g_mask[((size_t)3*SEQ + row)*(SEQ/32) + w] = m11;
        }
    }
}

// ---------------- fp16 2-group GEMM (A single, B=W*64 hi/lo) ----------------
// mode 0: A = gXf, B = QKV concat [1536][512]; epilogue -> gQ/gK/gV fp16 (/64).
// mode 1: A = gO,  B = Wo*64 [512][512];       epilogue -> fp32 out (/64).
// Stage (40KB): A 64x128B @0 (8KB), Bh 128x128B @8192, Bl @24576.
#define PJ_BUF 40960
__global__ __launch_bounds__(256, 2) void proj_gemm(float* __restrict__ Yout, int mode) {
    extern __shared__ char dsm[];
    u32 sb = (smem_u32(dsm) + 127) & ~127u;

    const __half* A_f = mode ? gO : gXf;
    const __half* B_h = mode ? gWh[3] : gWh[0];
    const __half* B_l = mode ? gWl[3] : gWl[0];

    int tid = threadIdx.x, lane = tid & 31, warp = tid >> 5;
    int t4 = lane & 3, t8 = lane >> 2;
    int mrl = lane & 7, mm = lane >> 3;
    int wm = warp & 1, wn = warp >> 1;            // 2 x 4 warps, warp tile 32x32
    int m0 = blockIdx.x * 64, n0 = blockIdx.y * 128;

    // per buffer: A 512 + B 2048 = 2560 16B-copies; 10 per thread
    #define PJ_ISSUE(c, buf) do { \
        _Pragma("unroll") \
        for (int q = 0; q < 10; q++) { \
            int idx = tid + q*256; \
            const __half* s; u32 d; \
            if (idx < 512) { \
                int r = idx >> 3, ch = idx & 7; \
                s = A_f + (size_t)(m0 + r)*DIM + (c)*64 + ch*8; \
                d = sb + (buf)*PJ_BUF + r*128 + ((ch ^ (r & 7)) << 4); \
            } else { \
                int i2 = idx - 512; \
                int mtx = i2 >> 10, rem = i2 & 1023, r = rem >> 3, ch = rem & 7; \
                s = (mtx ? B_l : B_h) + (size_t)(n0 + r)*DIM + (c)*64 + ch*8; \
                d = sb + (buf)*PJ_BUF + 8192 + mtx*16384 + r*128 + ((ch ^ (r & 7)) << 4); \
            } \
            CPA16(d, s); \
        } \
        CPCOMMIT(); \
    } while (0)

    float C[2][4][4];
    #pragma unroll
    for (int a = 0; a < 2; a++)
        #pragma unroll
        for (int b = 0; b < 4; b++)
            #pragma unroll
            for (int c = 0; c < 4; c++) C[a][b][c] = 0.f;

    PJ_ISSUE(0, 0);
    PJ_ISSUE(1, 1);

    for (int c = 0; c < 8; c++) {
        if (c < 7) CPWAIT(1); else CPWAIT(0);
        __syncthreads();
        u32 bb = sb + (c & 1)*PJ_BUF;

        #pragma unroll
        for (int ks = 0; ks < 4; ks++) {
            u32 AF[2][4], BH[4][2], BL[4][2];
            int ch = 2*ks + (mm >> 1);
            #pragma unroll
            for (int fm = 0; fm < 2; fm++) {
                int row = wm*32 + fm*16 + (mm & 1)*8 + mrl;
                u32 a = bb + row*128 + ((ch ^ (row & 7)) << 4);
                LDM4(AF[fm][0], AF[fm][1], AF[fm][2], AF[fm][3], a);
            }
            #pragma unroll
            for (int p = 0; p < 2; p++) {
                int row = wn*32 + p*16 + (mm & 1)*8 + mrl;
                u32 aH = bb + 8192 + row*128 + ((ch ^ (row & 7)) << 4);
                LDM4(BH[2*p][0], BH[2*p+1][0], BH[2*p][1], BH[2*p+1][1], aH);
                LDM4(BL[2*p][0], BL[2*p+1][0], BL[2*p][1], BL[2*p+1][1], aH + 16384);
            }
            #pragma unroll
            for (int fm = 0; fm < 2; fm++)
                #pragma unroll
                for (int fn = 0; fn < 4; fn++) {
                    MMAH(C[fm][fn], AF[fm], BH[fn]);
                    MMAH(C[fm][fn], AF[fm], BL[fn]);
                }
        }
        __syncthreads();
        if (c + 2 < 8) PJ_ISSUE(c + 2, c & 1);
    }

    #pragma unroll
    for (int fm = 0; fm < 2; fm++) {
        int rA = m0 + wm*32 + fm*16 + t8;
        #pragma unroll
        for (int fn = 0; fn < 4; fn++) {
            int n = n0 + wn*32 + fn*8 + 2*t4;
            float c0 = C[fm][fn][0], c1 = C[fm][fn][1];
            float c2 = C[fm][fn][2], c3 = C[fm][fn][3];
            if (mode) {
                *(float2*)(Yout + (size_t)rA*DIM + n)     = make_float2(c0*INVWS, c1*INVWS);
                *(float2*)(Yout + (size_t)(rA+8)*DIM + n) = make_float2(c2*INVWS, c3*INVWS);
            } else {
                int osel = n >> 9, col = n & 511;
                __half* dst = osel == 0 ? gQ : osel == 1 ? gK : gV;
                float sc = (osel == 0) ? 0.125f * LOG2E * INVWS : INVWS;
                *(u32*)(dst + (size_t)rA*DIM + col)     = cvtf16x2(c0*sc, c1*sc);
                *(u32*)(dst + (size_t)(rA+8)*DIM + col) = cvtf16x2(c2*sc, c3*sc);
            }
        }
    }
}

// ---------------- flash attention (fp16 mma, PRMT AND-masks) ----------------
// CTA: 128 i-rows of one (b,h); 8 warps x 16 rows; 32 j-tiles of 64.
// 3 stages, 1 sync/iter; row sums via P @ ones on the tensor pipe.
#define AT_STG 16384   // per stage: K 8KB @0, V 8KB @8192
__global__ __launch_bounds__(256, 2) void attn_kernel() {
    extern __shared__ char dsm[];
    u32 sb = (smem_u32(dsm) + 127) & ~127u;

    int tid = threadIdx.x, lane = tid & 31, warp = tid >> 5;
    int t4 = lane & 3, t8 = lane >> 2;
    int mrl = lane & 7, mm = lane >> 3;
    int i0 = blockIdx.x * 128;
    int bh = blockIdx.y, b = bh >> 3, hh = bh & 7;
    int combo = b*2 + (hh & 1);

    #define AT_ISSUE(jt, st) do { \
        _Pragma("unroll") \
        for (int q = 0; q < 4; q++) { \
            int idx = tid + q*256; \
            int mtx = idx >> 9, rem = idx & 511, r = rem >> 3, ch = rem & 7; \
            const __half* s = (mtx ? gV : gK) + (size_t)(b*SEQ + (jt)*64 + r)*DIM + hh*DK + ch*8; \
            u32 d = sb + (st)*AT_STG + mtx*8192 + r*128 + ((ch ^ (r & 7)) << 4); \
            CPA16(d, s); \
        } \
        CPCOMMIT(); \
    } while (0)

    AT_ISSUE(0, 0);
    AT_ISSUE(1, 1);

    // Q fragments (fp16) held in registers for the whole kernel
    u32 QA[4][4];
    {
        size_t qbase = (size_t)(b*SEQ + i0 + warp*16 + t8)*DIM + hh*DK + 2*t4;
        #pragma unroll
        for (int ks = 0; ks < 4; ks++) {
            QA[ks][0] = *(const u32*)(gQ + qbase + ks*16);
            QA[ks][1] = *(const u32*)(gQ + qbase + ks*16 + 8*DIM);
            QA[ks][2] = *(const u32*)(gQ + qbase + ks*16 + 8);
            QA[ks][3] = *(const u32*)(gQ + qbase + ks*16 + 8*DIM + 8);
        }
    }

    const u32* mrowA = g_mask + ((size_t)combo*SEQ + i0 + warp*16 + t8)*(SEQ/32);
    const u32* mrowB = mrowA + 8*(SEQ/32);

    float O[8][4];
    #pragma unroll
    for (int f = 0; f < 8; f++)
        #pragma unroll
        for (int c = 0; c < 4; c++) O[f][c] = 0.f;
    float LS[4] = {0.f, 0.f, 0.f, 0.f};     // tensor-core row sums: LS[0]=rowA, LS[2]=rowB

    for (int t = 0; t < 32; t++) {
        if (t < 31) CPWAIT(1); else CPWAIT(0);
        __syncthreads();
        if (t + 2 < 32) AT_ISSUE(t + 2, (t + 2) % 3);
        u32 kb = sb + (t % 3)*AT_STG;
        u32 vb = kb + 8192;

        // mask words early (LDG hidden under S MMAs); preshift by 2*t4
        uint2 wA = *(const uint2*)(mrowA + (t << 1));
        uint2 wB = *(const uint2*)(mrowB + (t << 1));
        u64 sA64 = ((u64)wA.x | ((u64)wA.y << 32)) >> (2*t4);
        u64 sB64 = ((u64)wB.x | ((u64)wB.y << 32)) >> (2*t4);
        u32 aLo = (u32)sA64, aHi = (u32)(sA64 >> 32);
        u32 bLo = (u32)sB64, bHi = (u32)(sB64 >> 32);

        // S = Q K^T
        float S[8][4];
        #pragma unroll
        for (int f = 0; f < 8; f++)
            #pragma unroll
            for (int c = 0; c < 4; c++) S[f][c] = 0.f;

        #pragma unroll
        for (int ks = 0; ks < 4; ks++) {
            u32 BH[8][2];
            int ch = 2*ks + (mm >> 1);
            #pragma unroll
            for (int p = 0; p < 4; p++) {
                int row = 16*p + (mm & 1)*8 + mrl;
                u32 a = kb + row*128 + ((ch ^ (row & 7)) << 4);
                LDM4(BH[2*p][0], BH[2*p+1][0], BH[2*p][1], BH[2*p+1][1], a);
            }
            #pragma unroll
            for (int f = 0; f < 8; f++) MMAH(S[f], QA[ks], BH[f]);
        }

        // ex2 (unconditional) + fp16 pack + PRMT-expanded AND masks
        u32 PH[4][4];
        #pragma unroll
        for (int f = 0; f < 8; f++) {
            u32 uA = (f < 4 ? aLo : aHi) >> (8*(f & 3));
            u32 uB = (f < 4 ? bLo : bHi) >> (8*(f & 3));
            u32 r = ((uA << 7) & 0x80u) | ((uA << 14) & 0x8000u)
                  | ((uB << 23) & 0x800000u) | ((uB << 30) & 0x80000000u);
            u32 MA = prmt0(r, 0x9988u);
            u32 MB = prmt0(r, 0xBBAAu);
            float p0 = ex2f(S[f][0]);
            float p1 = ex2f(S[f][1]);
            float p2 = ex2f(S[f][2]);
            float p3 = ex2f(S[f][3]);
            int ks = f >> 1, o = (f & 1)*2;
            PH[ks][o]   = cvtf16x2(p0, p1) & MA;
            PH[ks][o+1] = cvtf16x2(p2, p3) & MB;
        }

        // O += P V; LS += P @ ones (row sums on the tensor pipe)
        #pragma unroll
        for (int ks = 0; ks < 4; ks++) {
            u32 VH[8][2];
            int row = 16*ks + (mm >> 1)*8 + mrl;
            #pragma unroll
            for (int p = 0; p < 4; p++) {
                int ch = 2*p + (mm & 1);
                u32 a = vb + row*128 + ((ch ^ (row & 7)) << 4);
                LDM4T(VH[2*p][0], VH[2*p+1][0], VH[2*p][1], VH[2*p+1][1], a);
            }
            #pragma unroll
            for (int f = 0; f < 8; f++) MMAH(O[f], PH[ks], VH[f]);
            MMAH2(LS, PH[ks], ONESF16, ONESF16);
        }
    }

    float invA = (LS[0] > 0.f) ? 1.0f / LS[0] : 0.f;
    float invB = (LS[2] > 0.f) ? 1.0f / LS[2] : 0.f;

    size_t obase = (size_t)(b*SEQ + i0 + warp*16 + t8)*DIM + hh*DK + 2*t4;
    #pragma unroll
    for (int f = 0; f < 8; f++) {
        *(u32*)(gO + obase + 8*f)         = cvtf16x2(O[f][0]*invA, O[f][1]*invA);
        *(u32*)(gO + obase + 8*f + 8*DIM) = cvtf16x2(O[f][2]*invB, O[f][3]*invB);
    }
}

// ---------------------------------------------------------------------------
extern "C" void kernel_launch(void* const* d_in, const int* in_sizes, int n_in,
                              void* d_out, int out_size)
{
    const float* x  = (const float*)d_in[0];
    const float* Wq = (const float*)d_in[1];
    const float* Wk = (const float*)d_in[2];
    const float* Wv = (const float*)d_in[3];
    const float* Wo = (const float*)d_in[4];
    const int* seq_mask     = (const int*)d_in[5];
    const int* sparse_masks = (const int*)d_in[6];
    float* out = (float*)d_out;

    cudaFuncSetAttribute(proj_gemm,   cudaFuncAttributeMaxDynamicSharedMemorySize, 2*PJ_BUF);
    cudaFuncSetAttribute(attn_kernel, cudaFuncAttributeMaxDynamicSharedMemorySize, 3*AT_STG);

    mask_prep<<<SEQ, 256>>>(seq_mask, sparse_masks);
    conv_all<<<2048 + 4*256, 256>>>(x, Wq, Wk, Wv, Wo);

    proj_gemm<<<dim3(MT/64, 1536/128), 256, 2*PJ_BUF>>>(nullptr, 0); // fused QKV
    attn_kernel<<<dim3(SEQ/128, BATCH*NHEAD), 256, 3*AT_STG>>>();
    proj_gemm<<<dim3(MT/64, DIM/128), 256, 2*PJ_BUF>>>(out, 1);      // O @ Wo^T
    (void)in_sizes; (void)n_in; (void)out_size;
}

// round 12
// speedup vs baseline: 1.7627x; 1.0294x over previous
#include <cuda_runtime.h>
#include <cuda_bf16.h>
#include <cuda_fp16.h>
#include <math.h>

typedef unsigned int u32;
typedef unsigned long long u64;

#define BATCH 2
#define SEQ   2048
#define DIM   512
#define NHEAD 8
#define DK    64
#define MT    (BATCH*SEQ)
#define LOG2E 1.4426950408889634f
#define ONESF16 0x3C003C00u
#define WSCALE 64.0f
#define INVWS  (1.0f/64.0f)

// ---------------- global scratch (alloc-free) ------------------------------
__device__ __half gXf[MT*DIM];                   // x as fp16
__device__ __half gWh[4][DIM*DIM], gWl[4][DIM*DIM];  // W*64 fp16 hi/lo; 0..2 QKV contig, 3 = O
__device__ __half gQ[MT*DIM];                    // pre-scaled 0.125*log2e
__device__ __half gK[MT*DIM];
__device__ __half gV[MT*DIM];
__device__ __half gO[MT*DIM];                    // attn output, fp16
__device__ u32 g_mask[4*SEQ*(SEQ/32)];           // [b*2+par][row][word] compact bits

// ---------------- helpers ---------------------------------------------------
static __device__ __forceinline__ u32 smem_u32(const void* p) {
    u32 a; asm("{ .reg .u64 t; cvta.to.shared.u64 t, %1; cvt.u32.u64 %0, t; }" : "=r"(a) : "l"(p));
    return a;
}
static __device__ __forceinline__ void splith(float v, __half& hi, __half& lo) {
    hi = __float2half_rn(v);
    lo = __float2half_rn(v - __half2float(hi));
}
static __device__ __forceinline__ u32 packh(__half a, __half b) {
    return (u32)__half_as_ushort(a) | ((u32)__half_as_ushort(b) << 16);
}
// packs {lo, hi} halves
static __device__ __forceinline__ u32 cvtf16x2(float lo, float hi) {
    u32 d; asm("cvt.rn.f16x2.f32 %0, %1, %2;" : "=r"(d) : "f"(hi), "f"(lo)); return d;
}
static __device__ __forceinline__ u32 prmt0(u32 a, u32 sel) {
    u32 d; asm("prmt.b32 %0, %1, %2, %3;" : "=r"(d) : "r"(a), "r"(0u), "r"(sel)); return d;
}
static __device__ __forceinline__ u32 ex2h2(u32 x) {
    u32 d; asm("ex2.approx.f16x2 %0, %1;" : "=r"(d) : "r"(x)); return d;
}

#define LDM4(r0,r1,r2,r3,a) \
    asm volatile("ldmatrix.sync.aligned.m8n8.x4.shared.b16 {%0,%1,%2,%3}, [%4];" \
        : "=r"(r0),"=r"(r1),"=r"(r2),"=r"(r3) : "r"(a))
#define LDM4T(r0,r1,r2,r3,a) \
    asm volatile("ldmatrix.sync.aligned.m8n8.x4.trans.shared.b16 {%0,%1,%2,%3}, [%4];" \
        : "=r"(r0),"=r"(r1),"=r"(r2),"=r"(r3) : "r"(a))
#define MMAH(d,a,b) \
    asm volatile("mma.sync.aligned.m16n8k16.row.col.f32.f16.f16.f32 " \
        "{%0,%1,%2,%3}, {%4,%5,%6,%7}, {%8,%9}, {%0,%1,%2,%3};" \
        : "+f"((d)[0]),"+f"((d)[1]),"+f"((d)[2]),"+f"((d)[3]) \
        : "r"((a)[0]),"r"((a)[1]),"r"((a)[2]),"r"((a)[3]),"r"((b)[0]),"r"((b)[1]))
#define MMAH2(d,a,b0,b1) \
    asm volatile("mma.sync.aligned.m16n8k16.row.col.f32.f16.f16.f32 " \
        "{%0,%1,%2,%3}, {%4,%5,%6,%7}, {%8,%9}, {%0,%1,%2,%3};" \
        : "+f"((d)[0]),"+f"((d)[1]),"+f"((d)[2]),"+f"((d)[3]) \
        : "r"((a)[0]),"r"((a)[1]),"r"((a)[2]),"r"((a)[3]),"r"(b0),"r"(b1))

#define CPA16(d, s) asm volatile("cp.async.cg.shared.global [%0], [%1], 16;" :: "r"(d), "l"(s) : "memory")
#define CPCOMMIT()  asm volatile("cp.async.commit_group;" ::: "memory")
#define CPWAIT(n)   asm volatile("cp.async.wait_group %0;" :: "n"(n) : "memory")

// ---------------- conversions: x -> fp16; W*64 -> fp16 hi/lo ----------------
__global__ void conv_all(const float* __restrict__ x,
                         const float* __restrict__ Wq, const float* __restrict__ Wk,
                         const float* __restrict__ Wv, const float* __restrict__ Wo) {
    int blk = blockIdx.x;
    if (blk < 2048) {                      // x: 2M elements, single fp16
        int i = (blk * 256 + threadIdx.x) * 4;
        float4 v = *(const float4*)(x + i);
        *(uint2*)(gXf + i) = make_uint2(cvtf16x2(v.x, v.y), cvtf16x2(v.z, v.w));
    } else {                               // weights: 256 blocks each, *64 hi/lo
        int sel = (blk - 2048) >> 8, b2 = (blk - 2048) & 255;
        const float* src = sel == 0 ? Wq : sel == 1 ? Wk : sel == 2 ? Wv : Wo;
        int i = (b2 * 256 + threadIdx.x) * 4;
        float4 v = *(const float4*)(src + i);
        __half h0,l0,h1,l1,h2,l2,h3,l3;
        splith(v.x*WSCALE,h0,l0); splith(v.y*WSCALE,h1,l1);
        splith(v.z*WSCALE,h2,l2); splith(v.w*WSCALE,h3,l3);
        *(uint2*)(gWh[sel] + i) = make_uint2(packh(h0,h1), packh(h2,h3));
        *(uint2*)(gWl[sel] + i) = make_uint2(packh(l0,l1), packh(l2,l3));
    }
}

// ---------------- combined masks -> compact bit tables (batched loads) ------
__global__ void mask_prep(const int* __restrict__ seq_mask,
                          const int* __restrict__ sparse_masks) {
    int row  = blockIdx.x;
    int warp = threadIdx.x >> 5, lane = threadIdx.x & 31;
    const int* s0 = seq_mask     + (size_t)0*SEQ*SEQ + (size_t)row*SEQ;
    const int* s1 = seq_mask     + (size_t)1*SEQ*SEQ + (size_t)row*SEQ;
    const int* p0 = sparse_masks + (size_t)0*SEQ*SEQ + (size_t)row*SEQ;
    const int* p1 = sparse_masks + (size_t)1*SEQ*SEQ + (size_t)row*SEQ;
    int a0[8], a1[8], b0[8], b1[8];
    #pragma unroll
    for (int q = 0; q < 8; q++) {
        int j = (warp*8 + q)*32 + lane;
        a0[q] = s0[j]; a1[q] = s1[j]; b0[q] = p0[j]; b1[q] = p1[j];
    }
    #pragma unroll
    for (int q = 0; q < 8; q++) {
        int w = warp*8 + q;
        u32 m00 = __ballot_sync(0xffffffffu, (a0[q] & b0[q]) != 0);
        u32 m01 = __ballot_sync(0xffffffffu, (a0[q] & b1[q]) != 0);
        u32 m10 = __ballot_sync(0xffffffffu, (a1[q] & b0[q]) != 0);
        u32 m11 = __ballot_sync(0xffffffffu, (a1[q] & b1[q]) != 0);
        if (lane == 0) {
            g_mask[((size_t)0*SEQ + row)*(SEQ/32) + w] = m00;
            g_mask[((size_t)1*SEQ + row)*(SEQ/32) + w] = m01;
            g_mask[((size_t)2*SEQ + row)*(SEQ/32) + w] = m10;
            g_mask[((size_t)3*SEQ + row)*(SEQ/32) + w] = m11;
        }
    }
}

// ---------------- fp16 2-group GEMM (A single, B=W*64 hi/lo) ----------------
// mode 0: A = gXf, B = QKV concat [1536][512]; epilogue -> gQ/gK/gV fp16 (/64).
// mode 1: A = gO,  B = Wo*64 [512][512];       epilogue -> fp32 out (/64).
// Stage (40KB): A 64x128B @0 (8KB), Bh 128x128B @8192, Bl @24576.
#define PJ_BUF 40960
__global__ __launch_bounds__(256, 2) void proj_gemm(float* __restrict__ Yout, int mode) {
    extern __shared__ char dsm[];
    u32 sb = (smem_u32(dsm) + 127) & ~127u;

    const __half* A_f = mode ? gO : gXf;
    const __half* B_h = mode ? gWh[3] : gWh[0];
    const __half* B_l = mode ? gWl[3] : gWl[0];

    int tid = threadIdx.x, lane = tid & 31, warp = tid >> 5;
    int t4 = lane & 3, t8 = lane >> 2;
    int mrl = lane & 7, mm = lane >> 3;
    int wm = warp & 1, wn = warp >> 1;            // 2 x 4 warps, warp tile 32x32
    int m0 = blockIdx.x * 64, n0 = blockIdx.y * 128;

    // per buffer: A 512 + B 2048 = 2560 16B-copies; 10 per thread
    #define PJ_ISSUE(c, buf) do { \
        _Pragma("unroll") \
        for (int q = 0; q < 10; q++) { \
            int idx = tid + q*256; \
            const __half* s; u32 d; \
            if (idx < 512) { \
                int r = idx >> 3, ch = idx & 7; \
                s = A_f + (size_t)(m0 + r)*DIM + (c)*64 + ch*8; \
                d = sb + (buf)*PJ_BUF + r*128 + ((ch ^ (r & 7)) << 4); \
            } else { \
                int i2 = idx - 512; \
                int mtx = i2 >> 10, rem = i2 & 1023, r = rem >> 3, ch = rem & 7; \
                s = (mtx ? B_l : B_h) + (size_t)(n0 + r)*DIM + (c)*64 + ch*8; \
                d = sb + (buf)*PJ_BUF + 8192 + mtx*16384 + r*128 + ((ch ^ (r & 7)) << 4); \
            } \
            CPA16(d, s); \
        } \
        CPCOMMIT(); \
    } while (0)

    float C[2][4][4];
    #pragma unroll
    for (int a = 0; a < 2; a++)
        #pragma unroll
        for (int b = 0; b < 4; b++)
            #pragma unroll
            for (int c = 0; c < 4; c++) C[a][b][c] = 0.f;

    PJ_ISSUE(0, 0);
    PJ_ISSUE(1, 1);

    for (int c = 0; c < 8; c++) {
        if (c < 7) CPWAIT(1); else CPWAIT(0);
        __syncthreads();
        u32 bb = sb + (c & 1)*PJ_BUF;

        #pragma unroll
        for (int ks = 0; ks < 4; ks++) {
            u32 AF[2][4], BH[4][2], BL[4][2];
            int ch = 2*ks + (mm >> 1);
            #pragma unroll
            for (int fm = 0; fm < 2; fm++) {
                int row = wm*32 + fm*16 + (mm & 1)*8 + mrl;
                u32 a = bb + row*128 + ((ch ^ (row & 7)) << 4);
                LDM4(AF[fm][0], AF[fm][1], AF[fm][2], AF[fm][3], a);
            }
            #pragma unroll
            for (int p = 0; p < 2; p++) {
                int row = wn*32 + p*16 + (mm & 1)*8 + mrl;
                u32 aH = bb + 8192 + row*128 + ((ch ^ (row & 7)) << 4);
                LDM4(BH[2*p][0], BH[2*p+1][0], BH[2*p][1], BH[2*p+1][1], aH);
                LDM4(BL[2*p][0], BL[2*p+1][0], BL[2*p][1], BL[2*p+1][1], aH + 16384);
            }
            #pragma unroll
            for (int fm = 0; fm < 2; fm++)
                #pragma unroll
                for (int fn = 0; fn < 4; fn++) {
                    MMAH(C[fm][fn], AF[fm], BH[fn]);
                    MMAH(C[fm][fn], AF[fm], BL[fn]);
                }
        }
        __syncthreads();
        if (c + 2 < 8) PJ_ISSUE(c + 2, c & 1);
    }

    #pragma unroll
    for (int fm = 0; fm < 2; fm++) {
        int rA = m0 + wm*32 + fm*16 + t8;
        #pragma unroll
        for (int fn = 0; fn < 4; fn++) {
            int n = n0 + wn*32 + fn*8 + 2*t4;
            float c0 = C[fm][fn][0], c1 = C[fm][fn][1];
            float c2 = C[fm][fn][2], c3 = C[fm][fn][3];
            if (mode) {
                *(float2*)(Yout + (size_t)rA*DIM + n)     = make_float2(c0*INVWS, c1*INVWS);
                *(float2*)(Yout + (size_t)(rA+8)*DIM + n) = make_float2(c2*INVWS, c3*INVWS);
            } else {
                int osel = n >> 9, col = n & 511;
                __half* dst = osel == 0 ? gQ : osel == 1 ? gK : gV;
                float sc = (osel == 0) ? 0.125f * LOG2E * INVWS : INVWS;
                *(u32*)(dst + (size_t)rA*DIM + col)     = cvtf16x2(c0*sc, c1*sc);
                *(u32*)(dst + (size_t)(rA+8)*DIM + col) = cvtf16x2(c2*sc, c3*sc);
            }
        }
    }
}

// ---------------- flash attention (fp16 mma, f16x2 ex2, LOP3 mask) ----------
// CTA: 128 i-rows of one (b,h); 8 warps x 16 rows; 32 j-tiles of 64.
// 3 stages, 1 sync/iter; row sums via P @ ones on the tensor pipe.
// Mask: select -inf into the fp16 log2-domain input; ex2(-inf) = +0 exactly.
#define AT_STG 16384   // per stage: K 8KB @0, V 8KB @8192
__global__ __launch_bounds__(256, 2) void attn_kernel() {
    extern __shared__ char dsm[];
    u32 sb = (smem_u32(dsm) + 127) & ~127u;

    int tid = threadIdx.x, lane = tid & 31, warp = tid >> 5;
    int t4 = lane & 3, t8 = lane >> 2;
    int mrl = lane & 7, mm = lane >> 3;
    int i0 = blockIdx.x * 128;
    int bh = blockIdx.y, b = bh >> 3, hh = bh & 7;
    int combo = b*2 + (hh & 1);

    #define AT_ISSUE(jt, st) do { \
        _Pragma("unroll") \
        for (int q = 0; q < 4; q++) { \
            int idx = tid + q*256; \
            int mtx = idx >> 9, rem = idx & 511, r = rem >> 3, ch = rem & 7; \
            const __half* s = (mtx ? gV : gK) + (size_t)(b*SEQ + (jt)*64 + r)*DIM + hh*DK + ch*8; \
            u32 d = sb + (st)*AT_STG + mtx*8192 + r*128 + ((ch ^ (r & 7)) << 4); \
            CPA16(d, s); \
        } \
        CPCOMMIT(); \
    } while (0)

    AT_ISSUE(0, 0);
    AT_ISSUE(1, 1);

    // Q fragments (fp16) held in registers for the whole kernel
    u32 QA[4][4];
    {
        size_t qbase = (size_t)(b*SEQ + i0 + warp*16 + t8)*DIM + hh*DK + 2*t4;
        #pragma unroll
        for (int ks = 0; ks < 4; ks++) {
            QA[ks][0] = *(const u32*)(gQ + qbase + ks*16);
            QA[ks][1] = *(const u32*)(gQ + qbase + ks*16 + 8*DIM);
            QA[ks][2] = *(const u32*)(gQ + qbase + ks*16 + 8);
            QA[ks][3] = *(const u32*)(gQ + qbase + ks*16 + 8*DIM + 8);
        }
    }

    const u32* mrowA = g_mask + ((size_t)combo*SEQ + i0 + warp*16 + t8)*(SEQ/32);
    const u32* mrowB = mrowA + 8*(SEQ/32);

    float O[8][4];
    #pragma unroll
    for (int f = 0; f < 8; f++)
        #pragma unroll
        for (int c = 0; c < 4; c++) O[f][c] = 0.f;
    float LS[4] = {0.f, 0.f, 0.f, 0.f};     // tensor-core row sums: LS[0]=rowA, LS[2]=rowB

    for (int t = 0; t < 32; t++) {
        if (t < 31) CPWAIT(1); else CPWAIT(0);
        __syncthreads();
        if (t + 2 < 32) AT_ISSUE(t + 2, (t + 2) % 3);
        u32 kb = sb + (t % 3)*AT_STG;
        u32 vb = kb + 8192;

        // mask words early (LDG hidden under S MMAs); preshift by 2*t4
        uint2 wA = *(const uint2*)(mrowA + (t << 1));
        uint2 wB = *(const uint2*)(mrowB + (t << 1));
        u64 sA64 = ((u64)wA.x | ((u64)wA.y << 32)) >> (2*t4);
        u64 sB64 = ((u64)wB.x | ((u64)wB.y << 32)) >> (2*t4);
        u32 aLo = (u32)sA64, aHi = (u32)(sA64 >> 32);
        u32 bLo = (u32)sB64, bHi = (u32)(sB64 >> 32);

        // S = Q K^T
        float S[8][4];
        #pragma unroll
        for (int f = 0; f < 8; f++)
            #pragma unroll
            for (int c = 0; c < 4; c++) S[f][c] = 0.f;

        #pragma unroll
        for (int ks = 0; ks < 4; ks++) {
            u32 BH[8][2];
            int ch = 2*ks + (mm >> 1);
            #pragma unroll
            for (int p = 0; p < 4; p++) {
                int row = 16*p + (mm & 1)*8 + mrl;
                u32 a = kb + row*128 + ((ch ^ (row & 7)) << 4);
                LDM4(BH[2*p][0], BH[2*p+1][0], BH[2*p][1], BH[2*p+1][1], a);
            }
            #pragma unroll
            for (int f = 0; f < 8; f++) MMAH(S[f], QA[ks], BH[f]);
        }

        // cvt to f16x2, LOP3 select -inf where masked, packed ex2
        u32 PH[4][4];
        #pragma unroll
        for (int f = 0; f < 8; f++) {
            u32 uA = (f < 4 ? aLo : aHi) >> (8*(f & 3));
            u32 uB = (f < 4 ? bLo : bHi) >> (8*(f & 3));
            u32 r = ((uA << 7) & 0x80u) | ((uA << 14) & 0x8000u)
                  | ((uB << 23) & 0x800000u) | ((uB << 30) & 0x80000000u);
            u32 MA = prmt0(r, 0x9988u);
            u32 MB = prmt0(r, 0xBBAAu);
            u32 sA16 = cvtf16x2(S[f][0], S[f][1]);
            u32 sB16 = cvtf16x2(S[f][2], S[f][3]);
            u32 inA = (sA16 & MA) | (0xFC00FC00u & ~MA);   // single LOP3
            u32 inB = (sB16 & MB) | (0xFC00FC00u & ~MB);
            int ks = f >> 1, o = (f & 1)*2;
            PH[ks][o]   = ex2h2(inA);
            PH[ks][o+1] = ex2h2(inB);
        }

        // O += P V; LS += P @ ones (row sums on the tensor pipe)
        #pragma unroll
        for (int ks = 0; ks < 4; ks++) {
            u32 VH[8][2];
            int row = 16*ks + (mm >> 1)*8 + mrl;
            #pragma unroll
            for (int p = 0; p < 4; p++) {
                int ch = 2*p + (mm & 1);
                u32 a = vb + row*128 + ((ch ^ (row & 7)) << 4);
                LDM4T(VH[2*p][0], VH[2*p+1][0], VH[2*p][1], VH[2*p+1][1], a);
            }
            #pragma unroll
            for (int f = 0; f < 8; f++) MMAH(O[f], PH[ks], VH[f]);
            MMAH2(LS, PH[ks], ONESF16, ONESF16);
        }
    }

    float invA = (LS[0] > 0.f) ? 1.0f / LS[0] : 0.f;
    float invB = (LS[2] > 0.f) ? 1.0f / LS[2] : 0.f;

    size_t obase = (size_t)(b*SEQ + i0 + warp*16 + t8)*DIM + hh*DK + 2*t4;
    #pragma unroll
    for (int f = 0; f < 8; f++) {
        *(u32*)(gO + obase + 8*f)         = cvtf16x2(O[f][0]*invA, O[f][1]*invA);
        *(u32*)(gO + obase + 8*f + 8*DIM) = cvtf16x2(O[f][2]*invB, O[f][3]*invB);
    }
}

// ---------------------------------------------------------------------------
extern "C" void kernel_launch(void* const* d_in, const int* in_sizes, int n_in,
                              void* d_out, int out_size)
{
    const float* x  = (const float*)d_in[0];
    const float* Wq = (const float*)d_in[1];
    const float* Wk = (const float*)d_in[2];
    const float* Wv = (const float*)d_in[3];
    const float* Wo = (const float*)d_in[4];
    const int* seq_mask     = (const int*)d_in[5];
    const int* sparse_masks = (const int*)d_in[6];
    float* out = (float*)d_out;

    cudaFuncSetAttribute(proj_gemm,   cudaFuncAttributeMaxDynamicSharedMemorySize, 2*PJ_BUF);
    cudaFuncSetAttribute(attn_kernel, cudaFuncAttributeMaxDynamicSharedMemorySize, 3*AT_STG);

    mask_prep<<<SEQ, 256>>>(seq_mask, sparse_masks);
    conv_all<<<2048 + 4*256, 256>>>(x, Wq, Wk, Wv, Wo);

    proj_gemm<<<dim3(MT/64, 1536/128), 256, 2*PJ_BUF>>>(nullptr, 0); // fused QKV
    attn_kernel<<<dim3(SEQ/128, BATCH*NHEAD), 256, 3*AT_STG>>>();
    proj_gemm<<<dim3(MT/64, DIM/128), 256, 2*PJ_BUF>>>(out, 1);      // O @ Wo^T
    (void)in_sizes; (void)n_in; (void)out_size;
}

// round 13
// speedup vs baseline: 2.1428x; 1.2156x over previous
#include <cuda_runtime.h>
#include <cuda_bf16.h>
#include <cuda_fp16.h>
#include <math.h>

typedef unsigned int u32;
typedef unsigned long long u64;

#define BATCH 2
#define SEQ   2048
#define DIM   512
#define NHEAD 8
#define DK    64
#define MT    (BATCH*SEQ)
#define LOG2E 1.4426950408889634f
#define ONESF16 0x3C003C00u
#define WSCALE 64.0f
#define INVWS  (1.0f/64.0f)

// ---------------- global scratch (alloc-free) ------------------------------
__device__ __half gXf[MT*DIM];                   // x as fp16
__device__ __half gW[4][DIM*DIM];                // W*64 fp16; 0..2 QKV contig, 3 = O
__device__ __half gQ[MT*DIM];                    // pre-scaled 0.125*log2e
__device__ __half gK[MT*DIM];
__device__ __half gV[MT*DIM];
__device__ __half gO[MT*DIM];                    // attn output, fp16
__device__ u32 g_mask[4*SEQ*(SEQ/32)];           // [b*2+par][row][word] compact bits

// ---------------- helpers ---------------------------------------------------
static __device__ __forceinline__ u32 smem_u32(const void* p) {
    u32 a; asm("{ .reg .u64 t; cvta.to.shared.u64 t, %1; cvt.u32.u64 %0, t; }" : "=r"(a) : "l"(p));
    return a;
}
// packs {lo, hi} halves
static __device__ __forceinline__ u32 cvtf16x2(float lo, float hi) {
    u32 d; asm("cvt.rn.f16x2.f32 %0, %1, %2;" : "=r"(d) : "f"(hi), "f"(lo)); return d;
}
static __device__ __forceinline__ u32 prmt0(u32 a, u32 sel) {
    u32 d; asm("prmt.b32 %0, %1, %2, %3;" : "=r"(d) : "r"(a), "r"(0u), "r"(sel)); return d;
}
static __device__ __forceinline__ u32 ex2h2(u32 x) {
    u32 d; asm("ex2.approx.f16x2 %0, %1;" : "=r"(d) : "r"(x)); return d;
}

#define LDM4(r0,r1,r2,r3,a) \
    asm volatile("ldmatrix.sync.aligned.m8n8.x4.shared.b16 {%0,%1,%2,%3}, [%4];" \
        : "=r"(r0),"=r"(r1),"=r"(r2),"=r"(r3) : "r"(a))
#define LDM4T(r0,r1,r2,r3,a) \
    asm volatile("ldmatrix.sync.aligned.m8n8.x4.trans.shared.b16 {%0,%1,%2,%3}, [%4];" \
        : "=r"(r0),"=r"(r1),"=r"(r2),"=r"(r3) : "r"(a))
#define MMAH(d,a,b) \
    asm volatile("mma.sync.aligned.m16n8k16.row.col.f32.f16.f16.f32 " \
        "{%0,%1,%2,%3}, {%4,%5,%6,%7}, {%8,%9}, {%0,%1,%2,%3};" \
        : "+f"((d)[0]),"+f"((d)[1]),"+f"((d)[2]),"+f"((d)[3]) \
        : "r"((a)[0]),"r"((a)[1]),"r"((a)[2]),"r"((a)[3]),"r"((b)[0]),"r"((b)[1]))
#define MMAH2(d,a,b0,b1) \
    asm volatile("mma.sync.aligned.m16n8k16.row.col.f32.f16.f16.f32 " \
        "{%0,%1,%2,%3}, {%4,%5,%6,%7}, {%8,%9}, {%0,%1,%2,%3};" \
        : "+f"((d)[0]),"+f"((d)[1]),"+f"((d)[2]),"+f"((d)[3]) \
        : "r"((a)[0]),"r"((a)[1]),"r"((a)[2]),"r"((a)[3]),"r"(b0),"r"(b1))

#define CPA16(d, s) asm volatile("cp.async.cg.shared.global [%0], [%1], 16;" :: "r"(d), "l"(s) : "memory")
#define CPCOMMIT()  asm volatile("cp.async.commit_group;" ::: "memory")
#define CPWAIT(n)   asm volatile("cp.async.wait_group %0;" :: "n"(n) : "memory")

// ---------------- fused prep: x->fp16, W*64->fp16, mask bit tables ----------
// blocks [0,2048): x conv; [2048,3072): W conv; [3072,5120): mask rows.
__global__ void prep_all(const float* __restrict__ x,
                         const float* __restrict__ Wq, const float* __restrict__ Wk,
                         const float* __restrict__ Wv, const float* __restrict__ Wo,
                         const int* __restrict__ seq_mask,
                         const int* __restrict__ sparse_masks) {
    int blk = blockIdx.x;
    if (blk < 2048) {                      // x: 2M elements, single fp16
        int i = (blk * 256 + threadIdx.x) * 4;
        float4 v = *(const float4*)(x + i);
        *(uint2*)(gXf + i) = make_uint2(cvtf16x2(v.x, v.y), cvtf16x2(v.z, v.w));
    } else if (blk < 3072) {               // weights: 256 blocks each, *64 single fp16
        int sel = (blk - 2048) >> 8, b2 = (blk - 2048) & 255;
        const float* src = sel == 0 ? Wq : sel == 1 ? Wk : sel == 2 ? Wv : Wo;
        int i = (b2 * 256 + threadIdx.x) * 4;
        float4 v = *(const float4*)(src + i);
        *(uint2*)(gW[sel] + i) = make_uint2(cvtf16x2(v.x*WSCALE, v.y*WSCALE),
                                            cvtf16x2(v.z*WSCALE, v.w*WSCALE));
    } else {                               // mask rows
        int row  = blk - 3072;
        int warp = threadIdx.x >> 5, lane = threadIdx.x & 31;
        const int* s0 = seq_mask     + (size_t)0*SEQ*SEQ + (size_t)row*SEQ;
        const int* s1 = seq_mask     + (size_t)1*SEQ*SEQ + (size_t)row*SEQ;
        const int* p0 = sparse_masks + (size_t)0*SEQ*SEQ + (size_t)row*SEQ;
        const int* p1 = sparse_masks + (size_t)1*SEQ*SEQ + (size_t)row*SEQ;
        int a0[8], a1[8], b0[8], b1[8];
        #pragma unroll
        for (int q = 0; q < 8; q++) {
            int j = (warp*8 + q)*32 + lane;
            a0[q] = s0[j]; a1[q] = s1[j]; b0[q] = p0[j]; b1[q] = p1[j];
        }
        #pragma unroll
        for (int q = 0; q < 8; q++) {
            int w = warp*8 + q;
            u32 m00 = __ballot_sync(0xffffffffu, (a0[q] & b0[q]) != 0);
            u32 m01 = __ballot_sync(0xffffffffu, (a0[q] & b1[q]) != 0);
            u32 m10 = __ballot_sync(0xffffffffu, (a1[q] & b0[q]) != 0);
            u32 m11 = __ballot_sync(0xffffffffu, (a1[q] & b1[q]) != 0);
            if (lane == 0) {
                g_mask[((size_t)0*SEQ + row)*(SEQ/32) + w] = m00;
                g_mask[((size_t)1*SEQ + row)*(SEQ/32) + w] = m01;
                g_mask[((size_t)2*SEQ + row)*(SEQ/32) + w] = m10;
                g_mask[((size_t)3*SEQ + row)*(SEQ/32) + w] = m11;
            }
        }
    }
}

// ---------------- single-fp16 GEMM (A fp16, B = W*64 fp16) ------------------
// mode 0: A = gXf, B = QKV concat [1536][512]; epilogue -> gQ/gK/gV fp16 (/64).
// mode 1: A = gO,  B = Wo*64 [512][512];       epilogue -> fp32 out (/64).
// Stage (24KB): A 64x128B @0 (8KB), B 128x128B @8192 (16KB).
#define PJ_BUF 24576
__global__ __launch_bounds__(256, 3) void proj_gemm(float* __restrict__ Yout, int mode) {
    extern __shared__ char dsm[];
    u32 sb = (smem_u32(dsm) + 127) & ~127u;

    const __half* A_f = mode ? gO : gXf;
    const __half* B_f = mode ? gW[3] : gW[0];

    int tid = threadIdx.x, lane = tid & 31, warp = tid >> 5;
    int t4 = lane & 3, t8 = lane >> 2;
    int mrl = lane & 7, mm = lane >> 3;
    int wm = warp & 1, wn = warp >> 1;            // 2 x 4 warps, warp tile 32x32
    int m0 = blockIdx.x * 64, n0 = blockIdx.y * 128;

    // per buffer: A 512 + B 1024 = 1536 16B-copies; 6 per thread
    #define PJ_ISSUE(c, buf) do { \
        _Pragma("unroll") \
        for (int q = 0; q < 6; q++) { \
            int idx = tid + q*256; \
            const __half* s; u32 d; \
            if (idx < 512) { \
                int r = idx >> 3, ch = idx & 7; \
                s = A_f + (size_t)(m0 + r)*DIM + (c)*64 + ch*8; \
                d = sb + (buf)*PJ_BUF + r*128 + ((ch ^ (r & 7)) << 4); \
            } else { \
                int i2 = idx - 512; \
                int r = i2 >> 3, ch = i2 & 7; \
                s = B_f + (size_t)(n0 + r)*DIM + (c)*64 + ch*8; \
                d = sb + (buf)*PJ_BUF + 8192 + r*128 + ((ch ^ (r & 7)) << 4); \
            } \
            CPA16(d, s); \
        } \
        CPCOMMIT(); \
    } while (0)

    float C[2][4][4];
    #pragma unroll
    for (int a = 0; a < 2; a++)
        #pragma unroll
        for (int b = 0; b < 4; b++)
            #pragma unroll
            for (int c = 0; c < 4; c++) C[a][b][c] = 0.f;

    PJ_ISSUE(0, 0);
    PJ_ISSUE(1, 1);

    for (int c = 0; c < 8; c++) {
        if (c < 7) CPWAIT(1); else CPWAIT(0);
        __syncthreads();
        u32 bb = sb + (c & 1)*PJ_BUF;

        #pragma unroll
        for (int ks = 0; ks < 4; ks++) {
            u32 AF[2][4], BF[4][2];
            int ch = 2*ks + (mm >> 1);
            #pragma unroll
            for (int fm = 0; fm < 2; fm++) {
                int row = wm*32 + fm*16 + (mm & 1)*8 + mrl;
                u32 a = bb + row*128 + ((ch ^ (row & 7)) << 4);
                LDM4(AF[fm][0], AF[fm][1], AF[fm][2], AF[fm][3], a);
            }
            #pragma unroll
            for (int p = 0; p < 2; p++) {
                int row = wn*32 + p*16 + (mm & 1)*8 + mrl;
                u32 a = bb + 8192 + row*128 + ((ch ^ (row & 7)) << 4);
                LDM4(BF[2*p][0], BF[2*p+1][0], BF[2*p][1], BF[2*p+1][1], a);
            }
            #pragma unroll
            for (int fm = 0; fm < 2; fm++)
                #pragma unroll
                for (int fn = 0; fn < 4; fn++)
                    MMAH(C[fm][fn], AF[fm], BF[fn]);
        }
        __syncthreads();
        if (c + 2 < 8) PJ_ISSUE(c + 2, c & 1);
    }

    #pragma unroll
    for (int fm = 0; fm < 2; fm++) {
        int rA = m0 + wm*32 + fm*16 + t8;
        #pragma unroll
        for (int fn = 0; fn < 4; fn++) {
            int n = n0 + wn*32 + fn*8 + 2*t4;
            float c0 = C[fm][fn][0], c1 = C[fm][fn][1];
            float c2 = C[fm][fn][2], c3 = C[fm][fn][3];
            if (mode) {
                *(float2*)(Yout + (size_t)rA*DIM + n)     = make_float2(c0*INVWS, c1*INVWS);
                *(float2*)(Yout + (size_t)(rA+8)*DIM + n) = make_float2(c2*INVWS, c3*INVWS);
            } else {
                int osel = n >> 9, col = n & 511;
                __half* dst = osel == 0 ? gQ : osel == 1 ? gK : gV;
                float sc = (osel == 0) ? 0.125f * LOG2E * INVWS : INVWS;
                *(u32*)(dst + (size_t)rA*DIM + col)     = cvtf16x2(c0*sc, c1*sc);
                *(u32*)(dst + (size_t)(rA+8)*DIM + col) = cvtf16x2(c2*sc, c3*sc);
            }
        }
    }
}

// ---------------- flash attention (fp16 mma, f16x2 ex2, LOP3 mask) ----------
// CTA: 128 i-rows of one (b,h); 8 warps x 16 rows; 32 j-tiles of 64.
// 3 stages, 1 sync/iter; row sums via P @ ones on the tensor pipe.
// Mask: select -inf into the fp16 log2-domain input; ex2(-inf) = +0 exactly.
#define AT_STG 16384   // per stage: K 8KB @0, V 8KB @8192
__global__ __launch_bounds__(256, 2) void attn_kernel() {
    extern __shared__ char dsm[];
    u32 sb = (smem_u32(dsm) + 127) & ~127u;

    int tid = threadIdx.x, lane = tid & 31, warp = tid >> 5;
    int t4 = lane & 3, t8 = lane >> 2;
    int mrl = lane & 7, mm = lane >> 3;
    int i0 = blockIdx.x * 128;
    int bh = blockIdx.y, b = bh >> 3, hh = bh & 7;
    int combo = b*2 + (hh & 1);

    #define AT_ISSUE(jt, st) do { \
        _Pragma("unroll") \
        for (int q = 0; q < 4; q++) { \
            int idx = tid + q*256; \
            int mtx = idx >> 9, rem = idx & 511, r = rem >> 3, ch = rem & 7; \
            const __half* s = (mtx ? gV : gK) + (size_t)(b*SEQ + (jt)*64 + r)*DIM + hh*DK + ch*8; \
            u32 d = sb + (st)*AT_STG + mtx*8192 + r*128 + ((ch ^ (r & 7)) << 4); \
            CPA16(d, s); \
        } \
        CPCOMMIT(); \
    } while (0)

    AT_ISSUE(0, 0);
    AT_ISSUE(1, 1);

    // Q fragments (fp16) held in registers for the whole kernel
    u32 QA[4][4];
    {
        size_t qbase = (size_t)(b*SEQ + i0 + warp*16 + t8)*DIM + hh*DK + 2*t4;
        #pragma unroll
        for (int ks = 0; ks < 4; ks++) {
            QA[ks][0] = *(const u32*)(gQ + qbase + ks*16);
            QA[ks][1] = *(const u32*)(gQ + qbase + ks*16 + 8*DIM);
            QA[ks][2] = *(const u32*)(gQ + qbase + ks*16 + 8);
            QA[ks][3] = *(const u32*)(gQ + qbase + ks*16 + 8*DIM + 8);
        }
    }

    const u32* mrowA = g_mask + ((size_t)combo*SEQ + i0 + warp*16 + t8)*(SEQ/32);
    const u32* mrowB = mrowA + 8*(SEQ/32);

    float O[8][4];
    #pragma unroll
    for (int f = 0; f < 8; f++)
        #pragma unroll
        for (int c = 0; c < 4; c++) O[f][c] = 0.f;
    float LS[4] = {0.f, 0.f, 0.f, 0.f};     // tensor-core row sums: LS[0]=rowA, LS[2]=rowB

    for (int t = 0; t < 32; t++) {
        if (t < 31) CPWAIT(1); else CPWAIT(0);
        __syncthreads();
        if (t + 2 < 32) AT_ISSUE(t + 2, (t + 2) % 3);
        u32 kb = sb + (t % 3)*AT_STG;
        u32 vb = kb + 8192;

        // mask words early (LDG hidden under S MMAs); preshift by 2*t4
        uint2 wA = *(const uint2*)(mrowA + (t << 1));
        uint2 wB = *(const uint2*)(mrowB + (t << 1));
        u64 sA64 = ((u64)wA.x | ((u64)wA.y << 32)) >> (2*t4);
        u64 sB64 = ((u64)wB.x | ((u64)wB.y << 32)) >> (2*t4);
        u32 aLo = (u32)sA64, aHi = (u32)(sA64 >> 32);
        u32 bLo = (u32)sB64, bHi = (u32)(sB64 >> 32);

        // S = Q K^T
        float S[8][4];
        #pragma unroll
        for (int f = 0; f < 8; f++)
            #pragma unroll
            for (int c = 0; c < 4; c++) S[f][c] = 0.f;

        #pragma unroll
        for (int ks = 0; ks < 4; ks++) {
            u32 BH[8][2];
            int ch = 2*ks + (mm >> 1);
            #pragma unroll
            for (int p = 0; p < 4; p++) {
                int row = 16*p + (mm & 1)*8 + mrl;
                u32 a = kb + row*128 + ((ch ^ (row & 7)) << 4);
                LDM4(BH[2*p][0], BH[2*p+1][0], BH[2*p][1], BH[2*p+1][1], a);
            }
            #pragma unroll
            for (int f = 0; f < 8; f++) MMAH(S[f], QA[ks], BH[f]);
        }

        // cvt to f16x2, LOP3 select -inf where masked, packed ex2
        u32 PH[4][4];
        #pragma unroll
        for (int f = 0; f < 8; f++) {
            u32 uA = (f < 4 ? aLo : aHi) >> (8*(f & 3));
            u32 uB = (f < 4 ? bLo : bHi) >> (8*(f & 3));
            u32 r = ((uA << 7) & 0x80u) | ((uA << 14) & 0x8000u)
                  | ((uB << 23) & 0x800000u) | ((uB << 30) & 0x80000000u);
            u32 MA = prmt0(r, 0x9988u);
            u32 MB = prmt0(r, 0xBBAAu);
            u32 sA16 = cvtf16x2(S[f][0], S[f][1]);
            u32 sB16 = cvtf16x2(S[f][2], S[f][3]);
            u32 inA = (sA16 & MA) | (0xFC00FC00u & ~MA);   // single LOP3
            u32 inB = (sB16 & MB) | (0xFC00FC00u & ~MB);
            int ks = f >> 1, o = (f & 1)*2;
            PH[ks][o]   = ex2h2(inA);
            PH[ks][o+1] = ex2h2(inB);
        }

        // O += P V; LS += P @ ones (row sums on the tensor pipe)
        #pragma unroll
        for (int ks = 0; ks < 4; ks++) {
            u32 VH[8][2];
            int row = 16*ks + (mm >> 1)*8 + mrl;
            #pragma unroll
            for (int p = 0; p < 4; p++) {
                int ch = 2*p + (mm & 1);
                u32 a = vb + row*128 + ((ch ^ (row & 7)) << 4);
                LDM4T(VH[2*p][0], VH[2*p+1][0], VH[2*p][1], VH[2*p+1][1], a);
            }
            #pragma unroll
            for (int f = 0; f < 8; f++) MMAH(O[f], PH[ks], VH[f]);
            MMAH2(LS, PH[ks], ONESF16, ONESF16);
        }
    }

    float invA = (LS[0] > 0.f) ? 1.0f / LS[0] : 0.f;
    float invB = (LS[2] > 0.f) ? 1.0f / LS[2] : 0.f;

    size_t obase = (size_t)(b*SEQ + i0 + warp*16 + t8)*DIM + hh*DK + 2*t4;
    #pragma unroll
    for (int f = 0; f < 8; f++) {
        *(u32*)(gO + obase + 8*f)         = cvtf16x2(O[f][0]*invA, O[f][1]*invA);
        *(u32*)(gO + obase + 8*f + 8*DIM) = cvtf16x2(O[f][2]*invB, O[f][3]*invB);
    }
}

// ---------------------------------------------------------------------------
extern "C" void kernel_launch(void* const* d_in, const int* in_sizes, int n_in,
                              void* d_out, int out_size)
{
    const float* x  = (const float*)d_in[0];
    const float* Wq = (const float*)d_in[1];
    const float* Wk = (const float*)d_in[2];
    const float* Wv = (const float*)d_in[3];
    const float* Wo = (const float*)d_in[4];
    const int* seq_mask     = (const int*)d_in[5];
    const int* sparse_masks = (const int*)d_in[6];
    float* out = (float*)d_out;

    cudaFuncSetAttribute(proj_gemm,   cudaFuncAttributeMaxDynamicSharedMemorySize, 2*PJ_BUF);
    cudaFuncSetAttribute(attn_kernel, cudaFuncAttributeMaxDynamicSharedMemorySize, 3*AT_STG);

    prep_all<<<5120, 256>>>(x, Wq, Wk, Wv, Wo, seq_mask, sparse_masks);

    proj_gemm<<<dim3(MT/64, 1536/128), 256, 2*PJ_BUF>>>(nullptr, 0); // fused QKV
    attn_kernel<<<dim3(SEQ/128, BATCH*NHEAD), 256, 3*AT_STG>>>();
    proj_gemm<<<dim3(MT/64, DIM/128), 256, 2*PJ_BUF>>>(out, 1);      // O @ Wo^T
    (void)in_sizes; (void)n_in; (void)out_size;
}

// round 14
// speedup vs baseline: 2.1496x; 1.0032x over previous
#include <cuda_runtime.h>
#include <cuda_bf16.h>
#include <cuda_fp16.h>
#include <math.h>

typedef unsigned int u32;
typedef unsigned long long u64;

#define BATCH 2
#define SEQ   2048
#define DIM   512
#define NHEAD 8
#define DK    64
#define MT    (BATCH*SEQ)
#define LOG2E 1.4426950408889634f
#define ONESF16 0x3C003C00u
#define WSCALE 64.0f
#define INVWS  (1.0f/64.0f)

// ---------------- global scratch (alloc-free) ------------------------------
__device__ __half gXf[MT*DIM];                   // x as fp16
__device__ __half gW[4][DIM*DIM];                // W*64 fp16; 0..2 QKV contig, 3 = O
__device__ __half gQ[MT*DIM];                    // pre-scaled 0.125*log2e
__device__ __half gK[MT*DIM];
__device__ __half gV[MT*DIM];
__device__ __half gO[MT*DIM];                    // attn output, fp16
__device__ u32 g_mask[4*SEQ*(SEQ/32)];           // [b*2+par][row][word] compact bits

// ---------------- helpers ---------------------------------------------------
static __device__ __forceinline__ u32 smem_u32(const void* p) {
    u32 a; asm("{ .reg .u64 t; cvta.to.shared.u64 t, %1; cvt.u32.u64 %0, t; }" : "=r"(a) : "l"(p));
    return a;
}
// packs {lo, hi} halves
static __device__ __forceinline__ u32 cvtf16x2(float lo, float hi) {
    u32 d; asm("cvt.rn.f16x2.f32 %0, %1, %2;" : "=r"(d) : "f"(hi), "f"(lo)); return d;
}
static __device__ __forceinline__ u32 prmt0(u32 a, u32 sel) {
    u32 d; asm("prmt.b32 %0, %1, %2, %3;" : "=r"(d) : "r"(a), "r"(0u), "r"(sel)); return d;
}
static __device__ __forceinline__ u32 ex2h2(u32 x) {
    u32 d; asm("ex2.approx.f16x2 %0, %1;" : "=r"(d) : "r"(x)); return d;
}

#define LDM4(r0,r1,r2,r3,a) \
    asm volatile("ldmatrix.sync.aligned.m8n8.x4.shared.b16 {%0,%1,%2,%3}, [%4];" \
        : "=r"(r0),"=r"(r1),"=r"(r2),"=r"(r3) : "r"(a))
#define LDM4T(r0,r1,r2,r3,a) \
    asm volatile("ldmatrix.sync.aligned.m8n8.x4.trans.shared.b16 {%0,%1,%2,%3}, [%4];" \
        : "=r"(r0),"=r"(r1),"=r"(r2),"=r"(r3) : "r"(a))
#define MMAH(d,a,b) \
    asm volatile("mma.sync.aligned.m16n8k16.row.col.f32.f16.f16.f32 " \
        "{%0,%1,%2,%3}, {%4,%5,%6,%7}, {%8,%9}, {%0,%1,%2,%3};" \
        : "+f"((d)[0]),"+f"((d)[1]),"+f"((d)[2]),"+f"((d)[3]) \
        : "r"((a)[0]),"r"((a)[1]),"r"((a)[2]),"r"((a)[3]),"r"((b)[0]),"r"((b)[1]))
#define MMAH2(d,a,b0,b1) \
    asm volatile("mma.sync.aligned.m16n8k16.row.col.f32.f16.f16.f32 " \
        "{%0,%1,%2,%3}, {%4,%5,%6,%7}, {%8,%9}, {%0,%1,%2,%3};" \
        : "+f"((d)[0]),"+f"((d)[1]),"+f"((d)[2]),"+f"((d)[3]) \
        : "r"((a)[0]),"r"((a)[1]),"r"((a)[2]),"r"((a)[3]),"r"(b0),"r"(b1))

#define CPA16(d, s) asm volatile("cp.async.cg.shared.global [%0], [%1], 16;" :: "r"(d), "l"(s) : "memory")
#define CPCOMMIT()  asm volatile("cp.async.commit_group;" ::: "memory")
#define CPWAIT(n)   asm volatile("cp.async.wait_group %0;" :: "n"(n) : "memory")

// ---------------- fused prep: x->fp16, W*64->fp16, mask bit tables ----------
// blocks [0,2048): x conv; [2048,3072): W conv; [3072,5120): mask rows.
__global__ void prep_all(const float* __restrict__ x,
                         const float* __restrict__ Wq, const float* __restrict__ Wk,
                         const float* __restrict__ Wv, const float* __restrict__ Wo,
                         const int* __restrict__ seq_mask,
                         const int* __restrict__ sparse_masks) {
    int blk = blockIdx.x;
    if (blk < 2048) {                      // x: 2M elements, single fp16
        int i = (blk * 256 + threadIdx.x) * 4;
        float4 v = *(const float4*)(x + i);
        *(uint2*)(gXf + i) = make_uint2(cvtf16x2(v.x, v.y), cvtf16x2(v.z, v.w));
    } else if (blk < 3072) {               // weights: 256 blocks each, *64 single fp16
        int sel = (blk - 2048) >> 8, b2 = (blk - 2048) & 255;
        const float* src = sel == 0 ? Wq : sel == 1 ? Wk : sel == 2 ? Wv : Wo;
        int i = (b2 * 256 + threadIdx.x) * 4;
        float4 v = *(const float4*)(src + i);
        *(uint2*)(gW[sel] + i) = make_uint2(cvtf16x2(v.x*WSCALE, v.y*WSCALE),
                                            cvtf16x2(v.z*WSCALE, v.w*WSCALE));
    } else {                               // mask rows
        int row  = blk - 3072;
        int warp = threadIdx.x >> 5, lane = threadIdx.x & 31;
        const int* s0 = seq_mask     + (size_t)0*SEQ*SEQ + (size_t)row*SEQ;
        const int* s1 = seq_mask     + (size_t)1*SEQ*SEQ + (size_t)row*SEQ;
        const int* p0 = sparse_masks + (size_t)0*SEQ*SEQ + (size_t)row*SEQ;
        const int* p1 = sparse_masks + (size_t)1*SEQ*SEQ + (size_t)row*SEQ;
        int a0[8], a1[8], b0[8], b1[8];
        #pragma unroll
        for (int q = 0; q < 8; q++) {
            int j = (warp*8 + q)*32 + lane;
            a0[q] = s0[j]; a1[q] = s1[j]; b0[q] = p0[j]; b1[q] = p1[j];
        }
        #pragma unroll
        for (int q = 0; q < 8; q++) {
            int w = warp*8 + q;
            u32 m00 = __ballot_sync(0xffffffffu, (a0[q] & b0[q]) != 0);
            u32 m01 = __ballot_sync(0xffffffffu, (a0[q] & b1[q]) != 0);
            u32 m10 = __ballot_sync(0xffffffffu, (a1[q] & b0[q]) != 0);
            u32 m11 = __ballot_sync(0xffffffffu, (a1[q] & b1[q]) != 0);
            if (lane == 0) {
                g_mask[((size_t)0*SEQ + row)*(SEQ/32) + w] = m00;
                g_mask[((size_t)1*SEQ + row)*(SEQ/32) + w] = m01;
                g_mask[((size_t)2*SEQ + row)*(SEQ/32) + w] = m10;
                g_mask[((size_t)3*SEQ + row)*(SEQ/32) + w] = m11;
            }
        }
    }
}

// ---------------- single-fp16 GEMM (A fp16, B = W*64 fp16) ------------------
// mode 0: A = gXf, B = QKV concat [1536][512]; epilogue -> gQ/gK/gV fp16 (/64).
// mode 1: A = gO,  B = Wo*64 [512][512];       epilogue -> fp32 out (/64).
// Stage (24KB): A 64x128B @0 (8KB), B 128x128B @8192 (16KB).
#define PJ_BUF 24576
__global__ __launch_bounds__(256, 3) void proj_gemm(float* __restrict__ Yout, int mode) {
    extern __shared__ char dsm[];
    u32 sb = (smem_u32(dsm) + 127) & ~127u;

    const __half* A_f = mode ? gO : gXf;
    const __half* B_f = mode ? gW[3] : gW[0];

    int tid = threadIdx.x, lane = tid & 31, warp = tid >> 5;
    int t4 = lane & 3, t8 = lane >> 2;
    int mrl = lane & 7, mm = lane >> 3;
    int wm = warp & 1, wn = warp >> 1;            // 2 x 4 warps, warp tile 32x32
    int m0 = blockIdx.x * 64, n0 = blockIdx.y * 128;

    // per buffer: A 512 + B 1024 = 1536 16B-copies; 6 per thread
    #define PJ_ISSUE(c, buf) do { \
        _Pragma("unroll") \
        for (int q = 0; q < 6; q++) { \
            int idx = tid + q*256; \
            const __half* s; u32 d; \
            if (idx < 512) { \
                int r = idx >> 3, ch = idx & 7; \
                s = A_f + (size_t)(m0 + r)*DIM + (c)*64 + ch*8; \
                d = sb + (buf)*PJ_BUF + r*128 + ((ch ^ (r & 7)) << 4); \
            } else { \
                int i2 = idx - 512; \
                int r = i2 >> 3, ch = i2 & 7; \
                s = B_f + (size_t)(n0 + r)*DIM + (c)*64 + ch*8; \
                d = sb + (buf)*PJ_BUF + 8192 + r*128 + ((ch ^ (r & 7)) << 4); \
            } \
            CPA16(d, s); \
        } \
        CPCOMMIT(); \
    } while (0)

    float C[2][4][4];
    #pragma unroll
    for (int a = 0; a < 2; a++)
        #pragma unroll
        for (int b = 0; b < 4; b++)
            #pragma unroll
            for (int c = 0; c < 4; c++) C[a][b][c] = 0.f;

    PJ_ISSUE(0, 0);
    PJ_ISSUE(1, 1);

    for (int c = 0; c < 8; c++) {
        if (c < 7) CPWAIT(1); else CPWAIT(0);
        __syncthreads();
        u32 bb = sb + (c & 1)*PJ_BUF;

        #pragma unroll
        for (int ks = 0; ks < 4; ks++) {
            u32 AF[2][4], BF[4][2];
            int ch = 2*ks + (mm >> 1);
            #pragma unroll
            for (int fm = 0; fm < 2; fm++) {
                int row = wm*32 + fm*16 + (mm & 1)*8 + mrl;
                u32 a = bb + row*128 + ((ch ^ (row & 7)) << 4);
                LDM4(AF[fm][0], AF[fm][1], AF[fm][2], AF[fm][3], a);
            }
            #pragma unroll
            for (int p = 0; p < 2; p++) {
                int row = wn*32 + p*16 + (mm & 1)*8 + mrl;
                u32 a = bb + 8192 + row*128 + ((ch ^ (row & 7)) << 4);
                LDM4(BF[2*p][0], BF[2*p+1][0], BF[2*p][1], BF[2*p+1][1], a);
            }
            #pragma unroll
            for (int fm = 0; fm < 2; fm++)
                #pragma unroll
                for (int fn = 0; fn < 4; fn++)
                    MMAH(C[fm][fn], AF[fm], BF[fn]);
        }
        __syncthreads();
        if (c + 2 < 8) PJ_ISSUE(c + 2, c & 1);
    }

    #pragma unroll
    for (int fm = 0; fm < 2; fm++) {
        int rA = m0 + wm*32 + fm*16 + t8;
        #pragma unroll
        for (int fn = 0; fn < 4; fn++) {
            int n = n0 + wn*32 + fn*8 + 2*t4;
            float c0 = C[fm][fn][0], c1 = C[fm][fn][1];
            float c2 = C[fm][fn][2], c3 = C[fm][fn][3];
            if (mode) {
                *(float2*)(Yout + (size_t)rA*DIM + n)     = make_float2(c0*INVWS, c1*INVWS);
                *(float2*)(Yout + (size_t)(rA+8)*DIM + n) = make_float2(c2*INVWS, c3*INVWS);
            } else {
                int osel = n >> 9, col = n & 511;
                __half* dst = osel == 0 ? gQ : osel == 1 ? gK : gV;
                float sc = (osel == 0) ? 0.125f * LOG2E * INVWS : INVWS;
                *(u32*)(dst + (size_t)rA*DIM + col)     = cvtf16x2(c0*sc, c1*sc);
                *(u32*)(dst + (size_t)(rA+8)*DIM + col) = cvtf16x2(c2*sc, c3*sc);
            }
        }
    }
}

// ---------------- flash attention: 4 warps x 32 i-rows (2 groups of 16) -----
// Halves smem crossbar traffic per MMA vs 8x16 layout (K/V fragments read
// once per warp, used for 2 row-groups). 32 j-tiles of 64, 3 stages,
// 1 sync/iter; row sums via P @ ones on the tensor pipe.
#define AT_STG 16384   // per stage: K 8KB @0, V 8KB @8192
__global__ __launch_bounds__(128, 2) void attn_kernel() {
    extern __shared__ char dsm[];
    u32 sb = (smem_u32(dsm) + 127) & ~127u;

    int tid = threadIdx.x, lane = tid & 31, warp = tid >> 5;   // warp 0..3
    int t4 = lane & 3, t8 = lane >> 2;
    int mrl = lane & 7, mm = lane >> 3;
    int i0 = blockIdx.x * 128;
    int bh = blockIdx.y, b = bh >> 3, hh = bh & 7;
    int combo = b*2 + (hh & 1);

    // per stage: K 512 + V 512 = 1024 16B-copies; 8 per thread (128 thr)
    #define AT_ISSUE(jt, st) do { \
        _Pragma("unroll") \
        for (int q = 0; q < 8; q++) { \
            int idx = tid + q*128; \
            int mtx = idx >> 9, rem = idx & 511, r = rem >> 3, ch = rem & 7; \
            const __half* s = (mtx ? gV : gK) + (size_t)(b*SEQ + (jt)*64 + r)*DIM + hh*DK + ch*8; \
            u32 d = sb + (st)*AT_STG + mtx*8192 + r*128 + ((ch ^ (r & 7)) << 4); \
            CPA16(d, s); \
        } \
        CPCOMMIT(); \
    } while (0)

    AT_ISSUE(0, 0);
    AT_ISSUE(1, 1);

    // Q fragments (fp16): 2 groups of 16 rows, held for the whole kernel
    u32 QA[2][4][4];
    #pragma unroll
    for (int g = 0; g < 2; g++) {
        size_t qbase = (size_t)(b*SEQ + i0 + warp*32 + g*16 + t8)*DIM + hh*DK + 2*t4;
        #pragma unroll
        for (int ks = 0; ks < 4; ks++) {
            QA[g][ks][0] = *(const u32*)(gQ + qbase + ks*16);
            QA[g][ks][1] = *(const u32*)(gQ + qbase + ks*16 + 8*DIM);
            QA[g][ks][2] = *(const u32*)(gQ + qbase + ks*16 + 8);
            QA[g][ks][3] = *(const u32*)(gQ + qbase + ks*16 + 8*DIM + 8);
        }
    }

    const u32* mrowA0 = g_mask + ((size_t)combo*SEQ + i0 + warp*32 + t8)*(SEQ/32);
    const u32* mrowB0 = mrowA0 + 8*(SEQ/32);
    const u32* mrowA1 = mrowA0 + 16*(SEQ/32);
    const u32* mrowB1 = mrowA0 + 24*(SEQ/32);

    float O[2][8][4];
    #pragma unroll
    for (int g = 0; g < 2; g++)
        #pragma unroll
        for (int f = 0; f < 8; f++)
            #pragma unroll
            for (int c = 0; c < 4; c++) O[g][f][c] = 0.f;
    float LS[2][4];
    #pragma unroll
    for (int g = 0; g < 2; g++)
        #pragma unroll
        for (int c = 0; c < 4; c++) LS[g][c] = 0.f;

    for (int t = 0; t < 32; t++) {
        if (t < 31) CPWAIT(1); else CPWAIT(0);
        __syncthreads();
        if (t + 2 < 32) AT_ISSUE(t + 2, (t + 2) % 3);
        u32 kb = sb + (t % 3)*AT_STG;
        u32 vb = kb + 8192;

        // mask words for both groups (LDG hidden under S MMAs); preshift 2*t4
        uint2 wA0 = *(const uint2*)(mrowA0 + (t << 1));
        uint2 wB0 = *(const uint2*)(mrowB0 + (t << 1));
        uint2 wA1 = *(const uint2*)(mrowA1 + (t << 1));
        uint2 wB1 = *(const uint2*)(mrowB1 + (t << 1));
        u64 sh = 2*t4;
        u64 A0 = ((u64)wA0.x | ((u64)wA0.y << 32)) >> sh;
        u64 B0 = ((u64)wB0.x | ((u64)wB0.y << 32)) >> sh;
        u64 A1 = ((u64)wA1.x | ((u64)wA1.y << 32)) >> sh;
        u64 B1 = ((u64)wB1.x | ((u64)wB1.y << 32)) >> sh;
        u32 aLo[2] = {(u32)A0, (u32)A1}, aHi[2] = {(u32)(A0 >> 32), (u32)(A1 >> 32)};
        u32 bLo[2] = {(u32)B0, (u32)B1}, bHi[2] = {(u32)(B0 >> 32), (u32)(B1 >> 32)};

        // S = Q K^T for both row-groups (K fragments loaded once)
        float S[2][8][4];
        #pragma unroll
        for (int g = 0; g < 2; g++)
            #pragma unroll
            for (int f = 0; f < 8; f++)
                #pragma unroll
                for (int c = 0; c < 4; c++) S[g][f][c] = 0.f;

        #pragma unroll
        for (int ks = 0; ks < 4; ks++) {
            u32 BH[8][2];
            int ch = 2*ks + (mm >> 1);
            #pragma unroll
            for (int p = 0; p < 4; p++) {
                int row = 16*p + (mm & 1)*8 + mrl;
                u32 a = kb + row*128 + ((ch ^ (row & 7)) << 4);
                LDM4(BH[2*p][0], BH[2*p+1][0], BH[2*p][1], BH[2*p+1][1], a);
            }
            #pragma unroll
            for (int g = 0; g < 2; g++)
                #pragma unroll
                for (int f = 0; f < 8; f++) MMAH(S[g][f], QA[g][ks], BH[f]);
        }

        // cvt to f16x2, LOP3 select -inf where masked, packed ex2
        u32 PH[2][4][4];
        #pragma unroll
        for (int g = 0; g < 2; g++)
            #pragma unroll
            for (int f = 0; f < 8; f++) {
                u32 uA = (f < 4 ? aLo[g] : aHi[g]) >> (8*(f & 3));
                u32 uB = (f < 4 ? bLo[g] : bHi[g]) >> (8*(f & 3));
                u32 r = ((uA << 7) & 0x80u) | ((uA << 14) & 0x8000u)
                      | ((uB << 23) & 0x800000u) | ((uB << 30) & 0x80000000u);
                u32 MA = prmt0(r, 0x9988u);
                u32 MB = prmt0(r, 0xBBAAu);
                u32 sA16 = cvtf16x2(S[g][f][0], S[g][f][1]);
                u32 sB16 = cvtf16x2(S[g][f][2], S[g][f][3]);
                u32 inA = (sA16 & MA) | (0xFC00FC00u & ~MA);
                u32 inB = (sB16 & MB) | (0xFC00FC00u & ~MB);
                int ks = f >> 1, o = (f & 1)*2;
                PH[g][ks][o]   = ex2h2(inA);
                PH[g][ks][o+1] = ex2h2(inB);
            }

        // O += P V; LS += P @ ones (V fragments loaded once per warp)
        #pragma unroll
        for (int ks = 0; ks < 4; ks++) {
            u32 VH[8][2];
            int row = 16*ks + (mm >> 1)*8 + mrl;
            #pragma unroll
            for (int p = 0; p < 4; p++) {
                int ch = 2*p + (mm & 1);
                u32 a = vb + row*128 + ((ch ^ (row & 7)) << 4);
                LDM4T(VH[2*p][0], VH[2*p+1][0], VH[2*p][1], VH[2*p+1][1], a);
            }
            #pragma unroll
            for (int g = 0; g < 2; g++) {
                #pragma unroll
                for (int f = 0; f < 8; f++) MMAH(O[g][f], PH[g][ks], VH[f]);
                MMAH2(LS[g], PH[g][ks], ONESF16, ONESF16);
            }
        }
    }

    #pragma unroll
    for (int g = 0; g < 2; g++) {
        float invA = (LS[g][0] > 0.f) ? 1.0f / LS[g][0] : 0.f;
        float invB = (LS[g][2] > 0.f) ? 1.0f / LS[g][2] : 0.f;
        size_t obase = (size_t)(b*SEQ + i0 + warp*32 + g*16 + t8)*DIM + hh*DK + 2*t4;
        #pragma unroll
        for (int f = 0; f < 8; f++) {
            *(u32*)(gO + obase + 8*f)         = cvtf16x2(O[g][f][0]*invA, O[g][f][1]*invA);
            *(u32*)(gO + obase + 8*f + 8*DIM) = cvtf16x2(O[g][f][2]*invB, O[g][f][3]*invB);
        }
    }
}

// ---------------------------------------------------------------------------
extern "C" void kernel_launch(void* const* d_in, const int* in_sizes, int n_in,
                              void* d_out, int out_size)
{
    const float* x  = (const float*)d_in[0];
    const float* Wq = (const float*)d_in[1];
    const float* Wk = (const float*)d_in[2];
    const float* Wv = (const float*)d_in[3];
    const float* Wo = (const float*)d_in[4];
    const int* seq_mask     = (const int*)d_in[5];
    const int* sparse_masks = (const int*)d_in[6];
    float* out = (float*)d_out;

    cudaFuncSetAttribute(proj_gemm,   cudaFuncAttributeMaxDynamicSharedMemorySize, 2*PJ_BUF);
    cudaFuncSetAttribute(attn_kernel, cudaFuncAttributeMaxDynamicSharedMemorySize, 3*AT_STG);

    prep_all<<<5120, 256>>>(x, Wq, Wk, Wv, Wo, seq_mask, sparse_masks);

    proj_gemm<<<dim3(MT/64, 1536/128), 256, 2*PJ_BUF>>>(nullptr, 0); // fused QKV
    attn_kernel<<<dim3(SEQ/128, BATCH*NHEAD), 128, 3*AT_STG>>>();
    proj_gemm<<<dim3(MT/64, DIM/128), 256, 2*PJ_BUF>>>(out, 1);      // O @ Wo^T
    (void)in_sizes; (void)n_in; (void)out_size;
}